// round 2
// baseline (speedup 1.0000x reference)
#include <cuda_runtime.h>

// Shapes (fixed):
//  input_tensor: (8, 3, 256, 256)   d_in[0]
//  conv1_w:      (8, 3, 1, 1)       d_in[1]
//  conv1_b:      (8,)               d_in[2]
//  offset_w:     (27, 8, 3, 3)      d_in[3]
//  offset_b:     (27,)              d_in[4]
//  dcn_w:        (512, 8, 3, 3)     d_in[5]
//  out:          (8, 512, 128, 128) float32

#define NB   8
#define HH   256
#define WW   256
#define CC   8
#define HO   128
#define WO   128
#define NPOS (NB * HO * WO)      // 131072
#define NTILES (NPOS / 32)       // 4096
#define NSLICE 148

__device__ float g_y[NB * HH * WW * CC];        // [n][h][w][c]  16 MB channels-last
__device__ float g_off[NB * 27 * HO * WO];      // [n][ch][sp]   13.5 MB

typedef unsigned long long u64;

__device__ __forceinline__ u64 pack2(float lo, float hi) {
    u64 r; asm("mov.b64 %0, {%1, %2};" : "=l"(r) : "f"(lo), "f"(hi)); return r;
}
__device__ __forceinline__ void fma2(u64& d, u64 a, u64 b) {
    asm("fma.rn.f32x2 %0, %1, %2, %0;" : "+l"(d) : "l"(a), "l"(b));
}
__device__ __forceinline__ void unpack2(u64 v, float& lo, float& hi) {
    asm("mov.b64 {%0, %1}, %2;" : "=f"(lo), "=f"(hi) : "l"(v));
}

// ---------------- kernel 1: 1x1 conv (3->8) + leaky relu, channels-last, 4 px/thread ----
__global__ void k_conv1(const float* __restrict__ x,
                        const float* __restrict__ w1,
                        const float* __restrict__ b1) {
    int idx4 = blockIdx.x * blockDim.x + threadIdx.x;   // 131072 threads, 4 px each
    if (idx4 >= NB * HH * WW / 4) return;
    int base = idx4 << 2;
    int n  = base >> 16;
    int hw = base & 0xFFFF;
    float4 c0 = *(const float4*)(x + (size_t)(n * 3 + 0) * 65536 + hw);
    float4 c1 = *(const float4*)(x + (size_t)(n * 3 + 1) * 65536 + hw);
    float4 c2 = *(const float4*)(x + (size_t)(n * 3 + 2) * 65536 + hw);
    float w[24], bb[8];
#pragma unroll
    for (int i = 0; i < 24; i++) w[i] = __ldg(&w1[i]);
#pragma unroll
    for (int i = 0; i < 8; i++) bb[i] = __ldg(&b1[i]);

    float px0[4] = {c0.x, c0.y, c0.z, c0.w};
    float px1[4] = {c1.x, c1.y, c1.z, c1.w};
    float px2[4] = {c2.x, c2.y, c2.z, c2.w};
    float4* o = (float4*)(g_y + (size_t)base * 8);
#pragma unroll
    for (int p = 0; p < 4; p++) {
        float v[8];
#pragma unroll
        for (int c = 0; c < 8; c++) {
            float t = w[c * 3 + 0] * px0[p] + w[c * 3 + 1] * px1[p] +
                      w[c * 3 + 2] * px2[p] + bb[c];
            v[c] = t >= 0.f ? t : 0.1f * t;
        }
        o[p * 2 + 0] = make_float4(v[0], v[1], v[2], v[3]);
        o[p * 2 + 1] = make_float4(v[4], v[5], v[6], v[7]);
    }
}

// ---------------- kernel 2: 3x3 stride-2 conv (8->27) + bias; sigmoid on mask ----------
// f32x2-packed: weights in smem as [tap][ic][ocpair] u64 (oc padded 27->28).
__global__ void k_offset(const float* __restrict__ ow, const float* __restrict__ ob) {
    __shared__ u64 ws2[9 * 8 * 14];
    int tid = threadIdx.x;
    for (int i = tid; i < 9 * 8 * 14; i += 256) {
        int tap = i / 112;
        int rem = i - tap * 112;
        int ic = rem / 14;
        int p = rem - ic * 14;
        int oc0 = 2 * p, oc1 = 2 * p + 1;
        float v0 = ow[(oc0 * 8 + ic) * 9 + tap];
        float v1 = (oc1 < 27) ? ow[(oc1 * 8 + ic) * 9 + tap] : 0.f;
        ws2[i] = pack2(v0, v1);
    }
    __syncthreads();

    int idx = blockIdx.x * 256 + tid;            // n*16384 + sp
    int n = idx >> 14;
    int sp = idx & 16383;
    int ho = sp >> 7, wo = sp & 127;

    u64 acc2[14];
#pragma unroll
    for (int p = 0; p < 14; p++) acc2[p] = 0ull;

#pragma unroll 1
    for (int kh = 0; kh < 3; kh++) {
        int hy = 2 * ho - 1 + kh;
        if ((unsigned)hy >= HH) continue;
#pragma unroll 1
        for (int kw = 0; kw < 3; kw++) {
            int wx = 2 * wo - 1 + kw;
            if ((unsigned)wx >= WW) continue;
            const float4* yp = (const float4*)(g_y + ((size_t)((n * HH + hy) * WW + wx)) * 8);
            float4 u = yp[0], v = yp[1];
            float yv[8] = {u.x, u.y, u.z, u.w, v.x, v.y, v.z, v.w};
            int tap = kh * 3 + kw;
            const u64* wp = ws2 + tap * 112;
#pragma unroll
            for (int ic = 0; ic < 8; ic++) {
                u64 A = pack2(yv[ic], yv[ic]);
#pragma unroll
                for (int p = 0; p < 14; p++) fma2(acc2[p], A, wp[ic * 14 + p]);
            }
        }
    }

    float accf[28];
#pragma unroll
    for (int p = 0; p < 14; p++) unpack2(acc2[p], accf[2 * p], accf[2 * p + 1]);

    float* op = g_off + (size_t)n * 27 * 16384 + sp;
#pragma unroll
    for (int c = 0; c < 27; c++) {
        float v = accf[c] + __ldg(&ob[c]);
        if (c >= 18) v = 1.f / (1.f + __expf(-v));
        op[c * 16384] = v;
    }
}

// ---------------- kernel 3: deformable sampling + GEMM (persistent CTAs) --------------
// Grid = 296 = 2 channel-halves x 148 slices. Ws-half [72][256] resident in smem.
// Double-buffered duplicated colsT (float2 (v,v) entries) -> FFMA2 with zero pack movs.
// One __syncthreads per tile; sample(t+1) before gemm(t) so sampling latency overlaps
// other warps' FMA issue.

__device__ __forceinline__ void sample_tile(int tile, float2* colsT2) {
    int tid = threadIdx.x;
    int pbase = tile << 5;
    int n = pbase >> 14;
    int spbase = pbase & 16383;
    for (int t = tid; t < 288; t += 256) {
        int pos = t & 31;
        int k = t >> 5;                    // 0..8
        int sp = spbase + pos;
        int ho = sp >> 7, wo = sp & 127;
        const float* offp = g_off + (size_t)n * 27 * 16384 + sp;
        float dy = offp[(2 * k) * 16384];
        float dx = offp[(2 * k + 1) * 16384];
        float m  = offp[(18 + k) * 16384];
        int ky = k / 3;
        int kx = k - ky * 3;
        float py = (float)(2 * ho - 1 + ky) + dy;
        float px = (float)(2 * wo - 1 + kx) + dx;
        float y0f = floorf(py), x0f = floorf(px);
        float fy = py - y0f, fx = px - x0f;
        int y0 = (int)y0f, x0 = (int)x0f;
        float wy0 = 1.f - fy, wx0 = 1.f - fx;

        float a0 = 0, a1 = 0, a2 = 0, a3 = 0, a4 = 0, a5 = 0, a6 = 0, a7 = 0;
#pragma unroll
        for (int oy = 0; oy < 2; oy++) {
            int yy = y0 + oy;
            if ((unsigned)yy >= HH) continue;
            float wy = oy ? fy : wy0;
#pragma unroll
            for (int ox = 0; ox < 2; ox++) {
                int xx = x0 + ox;
                if ((unsigned)xx >= WW) continue;
                float wgt = wy * (ox ? fx : wx0);
                const float4* p = (const float4*)(g_y + ((size_t)((n * HH + yy) * WW + xx)) * 8);
                float4 u = p[0], v = p[1];
                a0 += wgt * u.x; a1 += wgt * u.y; a2 += wgt * u.z; a3 += wgt * u.w;
                a4 += wgt * v.x; a5 += wgt * v.y; a6 += wgt * v.z; a7 += wgt * v.w;
            }
        }
        float2* cw = colsT2 + k * 32 + pos;   // row kk = c*9+k, per-c stride = 288 entries
        a0 *= m; a1 *= m; a2 *= m; a3 *= m; a4 *= m; a5 *= m; a6 *= m; a7 *= m;
        cw[0 * 288] = make_float2(a0, a0);
        cw[1 * 288] = make_float2(a1, a1);
        cw[2 * 288] = make_float2(a2, a2);
        cw[3 * 288] = make_float2(a3, a3);
        cw[4 * 288] = make_float2(a4, a4);
        cw[5 * 288] = make_float2(a5, a5);
        cw[6 * 288] = make_float2(a6, a6);
        cw[7 * 288] = make_float2(a7, a7);
    }
}

__global__ void __launch_bounds__(256, 2)
k_dcn(const float* __restrict__ dw, float* __restrict__ out) {
    extern __shared__ float sm[];
    float*  Ws   = sm;                                  // [72][256] floats, kk-major
    float2* buf0 = (float2*)(sm + 72 * 256);            // [72][32] duplicated pairs
    float2* buf1 = buf0 + 72 * 32;

    int tid = threadIdx.x;
    int half = blockIdx.x & 1;
    int slice = blockIdx.x >> 1;

    // load this block's 256-channel half of W, transposed to [kk][oc_local]
    {
        const float* src = dw + (size_t)(half * 256 + tid) * 72;
#pragma unroll
        for (int kk = 0; kk < 72; kk++) Ws[kk * 256 + tid] = src[kk];
    }

    int pos_g = tid & 7;              // 8 groups of 4 positions
    int ch_g = tid >> 3;              // 32 groups of 8 channels
    const float* bp = Ws + ch_g * 8;

    int tile = slice;
    if (tile < NTILES) sample_tile(tile, buf0);
    __syncthreads();

    int cur = 0;
    for (; tile < NTILES; tile += NSLICE) {
        int nxt = tile + NSLICE;
        float2* bufc = cur ? buf1 : buf0;
        float2* bufn = cur ? buf0 : buf1;

        // sample next tile first: its load latency overlaps other warps' FMA issue
        if (nxt < NTILES) sample_tile(nxt, bufn);

        // ---- GEMM 32x256, f32x2, A operands pre-duplicated in smem ----
        const float2* ap = bufc + pos_g * 4;
        u64 acc[4][4];
#pragma unroll
        for (int i = 0; i < 4; i++)
#pragma unroll
            for (int j = 0; j < 4; j++) acc[i][j] = 0ull;

#pragma unroll 8
        for (int kk = 0; kk < 72; kk++) {
            ulonglong2 a01 = *(const ulonglong2*)(ap + kk * 32);
            ulonglong2 a23 = *(const ulonglong2*)(ap + kk * 32 + 2);
            ulonglong2 q0 = *(const ulonglong2*)(bp + kk * 256);
            ulonglong2 q1 = *(const ulonglong2*)(bp + kk * 256 + 4);
            fma2(acc[0][0], a01.x, q0.x); fma2(acc[0][1], a01.x, q0.y);
            fma2(acc[0][2], a01.x, q1.x); fma2(acc[0][3], a01.x, q1.y);
            fma2(acc[1][0], a01.y, q0.x); fma2(acc[1][1], a01.y, q0.y);
            fma2(acc[1][2], a01.y, q1.x); fma2(acc[1][3], a01.y, q1.y);
            fma2(acc[2][0], a23.x, q0.x); fma2(acc[2][1], a23.x, q0.y);
            fma2(acc[2][2], a23.x, q1.x); fma2(acc[2][3], a23.x, q1.y);
            fma2(acc[3][0], a23.y, q0.x); fma2(acc[3][1], a23.y, q0.y);
            fma2(acc[3][2], a23.y, q1.x); fma2(acc[3][3], a23.y, q1.y);
        }

        // ---- store: 8 channels x 4 consecutive positions ----
        int pbase = tile << 5;
        int n = pbase >> 14;
        int spbase = pbase & 16383;

        float lo[4][4], hi[4][4];
#pragma unroll
        for (int i = 0; i < 4; i++)
#pragma unroll
            for (int j = 0; j < 4; j++) unpack2(acc[i][j], lo[i][j], hi[i][j]);

        size_t outbase = ((size_t)(n * 512 + half * 256 + ch_g * 8)) * 16384 +
                         (size_t)(spbase + pos_g * 4);
#pragma unroll
        for (int j = 0; j < 8; j++) {
            int jp = j >> 1;
            float4 vv = (j & 1)
                ? make_float4(hi[0][jp], hi[1][jp], hi[2][jp], hi[3][jp])
                : make_float4(lo[0][jp], lo[1][jp], lo[2][jp], lo[3][jp]);
            *(float4*)(out + outbase + (size_t)j * 16384) = vv;
        }

        __syncthreads();   // bufn sampling complete for everyone; bufc free to overwrite
        cur ^= 1;
    }
}

// ---------------- launch ----------------
extern "C" void kernel_launch(void* const* d_in, const int* in_sizes, int n_in,
                              void* d_out, int out_size) {
    const float* x  = (const float*)d_in[0];
    const float* w1 = (const float*)d_in[1];
    const float* b1 = (const float*)d_in[2];
    const float* ow = (const float*)d_in[3];
    const float* ob = (const float*)d_in[4];
    const float* dw = (const float*)d_in[5];
    float* out = (float*)d_out;

    k_conv1<<<(NB * HH * WW / 4 + 255) / 256, 256>>>(x, w1, b1);
    k_offset<<<NPOS / 256, 256>>>(ow, ob);

    int smem = 72 * 256 * (int)sizeof(float) + 2 * 72 * 32 * (int)sizeof(float2); // 110592
    cudaFuncSetAttribute(k_dcn, cudaFuncAttributeMaxDynamicSharedMemorySize, smem);
    k_dcn<<<2 * NSLICE, 256, smem>>>(dw, out);
}

// round 4
// speedup vs baseline: 2.4286x; 2.4286x over previous
#include <cuda_runtime.h>
#include <cuda_bf16.h>
#include <cstdint>

// Shapes (fixed):
//  input_tensor: (8, 3, 256, 256)   d_in[0]
//  conv1_w:      (8, 3, 1, 1)       d_in[1]
//  conv1_b:      (8,)               d_in[2]
//  offset_w:     (27, 8, 3, 3)      d_in[3]
//  offset_b:     (27,)              d_in[4]
//  dcn_w:        (512, 8, 3, 3)     d_in[5]
//  out:          (8, 512, 128, 128) float32

#define NB   8
#define HH   256
#define WW   256
#define HO   128
#define WO   128
#define NPOS (NB * HO * WO)      // 131072
#define TPOS 64                  // positions per tile
#define NT   (NPOS / TPOS)       // 2048 tiles
#define NSLICE 148

__device__ float g_y[NB * HH * WW * 8];     // [n][h][w][c] channels-last
__device__ float g_off[NB * 27 * HO * WO];  // [n][ch][sp]

// smem byte layout for k_dcn (stride 336 = 84 words -> ldmatrix conflict-free)
#define W_STRIDE 336
#define A_STRIDE 336
#define SM_W 0
#define SM_A (256 * W_STRIDE)                 // 86016
#define SM_TOTAL (SM_A + TPOS * A_STRIDE)     // 107520

// ------------------------------------------------------------------ PTX utils
__device__ __forceinline__ uint32_t smem_u32(const void* p) {
    uint32_t a;
    asm("{ .reg .u64 t; cvta.to.shared.u64 t, %1; cvt.u32.u64 %0, t; }" : "=r"(a) : "l"(p));
    return a;
}
__device__ __forceinline__ void ldsm4(uint32_t* r, uint32_t a) {
    asm volatile("ldmatrix.sync.aligned.m8n8.x4.shared.b16 {%0,%1,%2,%3}, [%4];"
        : "=r"(r[0]), "=r"(r[1]), "=r"(r[2]), "=r"(r[3]) : "r"(a));
}
__device__ __forceinline__ void ldsm2(uint32_t* r, uint32_t a) {
    asm volatile("ldmatrix.sync.aligned.m8n8.x2.shared.b16 {%0,%1}, [%2];"
        : "=r"(r[0]), "=r"(r[1]) : "r"(a));
}
__device__ __forceinline__ void mma_bf16(float* d, const uint32_t* a, const uint32_t* b) {
    asm volatile("mma.sync.aligned.m16n8k16.row.col.f32.bf16.bf16.f32 "
        "{%0,%1,%2,%3}, {%4,%5,%6,%7}, {%8,%9}, {%0,%1,%2,%3};"
        : "+f"(d[0]), "+f"(d[1]), "+f"(d[2]), "+f"(d[3])
        : "r"(a[0]), "r"(a[1]), "r"(a[2]), "r"(a[3]), "r"(b[0]), "r"(b[1]));
}

// ---------------- kernel 1: 1x1 conv (3->8) + leaky relu, channels-last ----------------
__global__ void k_conv1(const float* __restrict__ x,
                        const float* __restrict__ w1,
                        const float* __restrict__ b1) {
    int idx = blockIdx.x * blockDim.x + threadIdx.x;
    if (idx >= NB * HH * WW) return;
    int n  = idx >> 16;
    int hw = idx & 0xFFFF;
    float x0 = x[(n * 3 + 0) * 65536 + hw];
    float x1 = x[(n * 3 + 1) * 65536 + hw];
    float x2 = x[(n * 3 + 2) * 65536 + hw];
    float v[8];
#pragma unroll
    for (int c = 0; c < 8; c++) {
        float t = __ldg(&w1[c * 3 + 0]) * x0 + __ldg(&w1[c * 3 + 1]) * x1 +
                  __ldg(&w1[c * 3 + 2]) * x2 + __ldg(&b1[c]);
        v[c] = t >= 0.f ? t : 0.1f * t;
    }
    float4* o = (float4*)(g_y + (size_t)idx * 8);
    o[0] = make_float4(v[0], v[1], v[2], v[3]);
    o[1] = make_float4(v[4], v[5], v[6], v[7]);
}

// ---------------- kernel 2: 3x3 stride-2 conv (8->27) + bias; sigmoid on mask ----------
__global__ void k_offset(const float* __restrict__ ow, const float* __restrict__ ob) {
    __shared__ float ws[27 * 9 * 8];
    int tid = threadIdx.x;
    for (int i = tid; i < 1944; i += 256) {
        int oc = i / 72;
        int rem = i - oc * 72;
        int ic = rem / 9;
        int tap = rem - ic * 9;
        ws[(oc * 9 + tap) * 8 + ic] = ow[i];
    }
    __syncthreads();

    int idx = blockIdx.x * 256 + tid;
    int n = idx >> 14;
    int sp = idx & 16383;
    int ho = sp >> 7, wo = sp & 127;

    float acc[27];
#pragma unroll
    for (int c = 0; c < 27; c++) acc[c] = 0.f;

#pragma unroll 1
    for (int kh = 0; kh < 3; kh++) {
        int hy = 2 * ho - 1 + kh;
        if ((unsigned)hy >= HH) continue;
#pragma unroll 1
        for (int kw = 0; kw < 3; kw++) {
            int wx = 2 * wo - 1 + kw;
            if ((unsigned)wx >= WW) continue;
            const float4* yp = (const float4*)(g_y + ((size_t)((n * HH + hy) * WW + wx)) * 8);
            float4 u = yp[0], v = yp[1];
            int tap = kh * 3 + kw;
#pragma unroll
            for (int oc = 0; oc < 27; oc++) {
                const float4* wp = (const float4*)(ws + (oc * 9 + tap) * 8);
                float4 a = wp[0], b = wp[1];
                acc[oc] += u.x * a.x + u.y * a.y + u.z * a.z + u.w * a.w +
                           v.x * b.x + v.y * b.y + v.z * b.z + v.w * b.w;
            }
        }
    }

    float* op = g_off + (size_t)n * 27 * 16384 + sp;
#pragma unroll
    for (int c = 0; c < 27; c++) {
        float v = acc[c] + __ldg(&ob[c]);
        if (c >= 18) v = 1.f / (1.f + __expf(-v));
        op[c * 16384] = v;
    }
}

// ---------------- kernel 3: deformable sampling + HMMA (mma.sync) GEMM -----------------
// Grid 296 = 2 channel-halves x 148 slices. Per tile: M=256 ch x N=64 pos x K=80.
// W (hi/lo bf16) resident in smem rows [ch][kk], samples [pos][kk]; both k-contiguous,
// stride 336B (conflict-free ldmatrix). 3-term split: AhBh + AlBh + AhBl.
// Warp tile: 64 ch x 32 pos (wid&3 -> ch group, wid>>2 -> pos group).

__global__ void __launch_bounds__(256, 2)
k_dcn(const float* __restrict__ dw, float* __restrict__ out) {
    extern __shared__ char smem[];
    uint32_t sb = smem_u32(smem);
    int tid = threadIdx.x, lane = tid & 31, wid = tid >> 5;
    int half = blockIdx.x & 1, slice = blockIdx.x >> 1;

    // zero all smem (covers kk 72..79 pads in W and A)
    for (int i = tid; i < SM_TOTAL / 16; i += 256)
        ((uint4*)smem)[i] = make_uint4(0, 0, 0, 0);
    __syncthreads();

    // W fill: W[ch][kk] with kk = tap*8 + c ; hi at +0, lo at +160 within row
    for (int i = tid; i < 256 * 72; i += 256) {
        int ch = i / 72, j = i - ch * 72;      // j = c*9 + tap
        int c = j / 9, k = j - c * 9;
        int kk = k * 8 + c;
        float w = dw[(size_t)(half * 256 + ch) * 72 + j];
        __nv_bfloat16 hb = __float2bfloat16(w);
        __nv_bfloat16 lb = __float2bfloat16(w - __bfloat162float(hb));
        *(__nv_bfloat16*)(smem + SM_W + ch * W_STRIDE + kk * 2) = hb;
        *(__nv_bfloat16*)(smem + SM_W + ch * W_STRIDE + 160 + kk * 2) = lb;
    }

    int warp_ch = wid & 3;          // 4 groups x 64 ch
    int warp_pos = wid >> 2;        // 2 groups x 32 pos
    int PW = warp_pos * 32;

    // per-lane ldmatrix base addresses
    // A-operand (W): lanes 0-15 -> rows (l&15), lanes 16-31 -> same rows, k+8 (byte +16)
    uint32_t wa_base = sb + SM_W + (uint32_t)(warp_ch * 64 + (lane & 15)) * W_STRIDE +
                       ((lane >> 4) << 4);
    // B-operand (samples): lanes 0-7 -> rows, lanes 8-15 -> rows, k+8
    uint32_t ba_base = sb + SM_A + (uint32_t)(PW + (lane & 7)) * A_STRIDE +
                       (((lane >> 3) & 1) << 4);

    int g = lane >> 2, tg = lane & 3;

    for (int tile = slice; tile < NT; tile += NSLICE) {
        int pbase = tile << 6;
        int n = pbase >> 14;
        int spbase = pbase & 16383;

        __syncthreads();   // previous tile's ldmatrix reads complete (and W fill, iter 0)

        // ---- sampling: 64 pos x 9 taps ----
        for (int t = tid; t < 576; t += 256) {
            int pos = t & 63;
            int k = t >> 6;                  // tap 0..8
            int sp = spbase + pos;
            int ho = sp >> 7, wo = sp & 127;
            const float* offp = g_off + (size_t)n * 27 * 16384 + sp;
            float dy = offp[(2 * k) * 16384];
            float dx = offp[(2 * k + 1) * 16384];
            float m  = offp[(18 + k) * 16384];
            int ky = k / 3, kx = k - ky * 3;
            float py = (float)(2 * ho - 1 + ky) + dy;
            float px = (float)(2 * wo - 1 + kx) + dx;
            float y0f = floorf(py), x0f = floorf(px);
            float fy = py - y0f, fx = px - x0f;
            int y0 = (int)y0f, x0 = (int)x0f;
            float wy0 = 1.f - fy, wx0 = 1.f - fx;

            float a[8] = {0, 0, 0, 0, 0, 0, 0, 0};
#pragma unroll
            for (int oy = 0; oy < 2; oy++) {
                int yy = y0 + oy;
                if ((unsigned)yy >= HH) continue;
                float wy = oy ? fy : wy0;
#pragma unroll
                for (int ox = 0; ox < 2; ox++) {
                    int xx = x0 + ox;
                    if ((unsigned)xx >= WW) continue;
                    float wgt = wy * (ox ? fx : wx0);
                    const float4* p =
                        (const float4*)(g_y + ((size_t)((n * HH + yy) * WW + xx)) * 8);
                    float4 u = p[0], v = p[1];
                    a[0] += wgt * u.x; a[1] += wgt * u.y; a[2] += wgt * u.z; a[3] += wgt * u.w;
                    a[4] += wgt * v.x; a[5] += wgt * v.y; a[6] += wgt * v.z; a[7] += wgt * v.w;
                }
            }
            uint32_t hi4[4], lo4[4];
#pragma unroll
            for (int i = 0; i < 4; i++) {
                float v0 = a[2 * i] * m, v1 = a[2 * i + 1] * m;
                __nv_bfloat162 h = __floats2bfloat162_rn(v0, v1);
                __nv_bfloat162 l = __floats2bfloat162_rn(v0 - __bfloat162float(h.x),
                                                         v1 - __bfloat162float(h.y));
                hi4[i] = *(uint32_t*)&h;
                lo4[i] = *(uint32_t*)&l;
            }
            char* arow = smem + SM_A + pos * A_STRIDE + k * 16;   // kk = k*8 + c
            *(uint4*)arow         = make_uint4(hi4[0], hi4[1], hi4[2], hi4[3]);
            *(uint4*)(arow + 160) = make_uint4(lo4[0], lo4[1], lo4[2], lo4[3]);
        }
        __syncthreads();

        // ---- MMA: 64ch x 32pos per warp, K=80, 3-term bf16 split ----
        float acc[4][4][4];
#pragma unroll
        for (int mt = 0; mt < 4; mt++)
#pragma unroll
            for (int nt = 0; nt < 4; nt++)
#pragma unroll
                for (int r = 0; r < 4; r++) acc[mt][nt][r] = 0.f;

#pragma unroll
        for (int ks = 0; ks < 5; ks++) {
            uint32_t ah[4][4], al[4][4];
#pragma unroll
            for (int mt = 0; mt < 4; mt++) {
                ldsm4(ah[mt], wa_base + (uint32_t)(mt * 16 * W_STRIDE) + ks * 32);
                ldsm4(al[mt], wa_base + (uint32_t)(mt * 16 * W_STRIDE) + 160 + ks * 32);
            }
#pragma unroll
            for (int nt = 0; nt < 4; nt++) {
                uint32_t bh[2], bl[2];
                ldsm2(bh, ba_base + (uint32_t)(nt * 8 * A_STRIDE) + ks * 32);
                ldsm2(bl, ba_base + (uint32_t)(nt * 8 * A_STRIDE) + 160 + ks * 32);
#pragma unroll
                for (int mt = 0; mt < 4; mt++) {
                    mma_bf16(acc[mt][nt], ah[mt], bh);
                    mma_bf16(acc[mt][nt], al[mt], bh);
                    mma_bf16(acc[mt][nt], ah[mt], bl);
                }
            }
        }

        // ---- epilogue: thread holds (ch = base+g [, +8], pos = PW+nt*8+2*tg [,+1]) ----
#pragma unroll
        for (int mt = 0; mt < 4; mt++) {
            int ch0 = half * 256 + warp_ch * 64 + mt * 16 + g;
            float* r0 = out + ((size_t)(n * 512 + ch0)) * 16384 + spbase + PW + 2 * tg;
            float* r1 = r0 + (size_t)8 * 16384;
#pragma unroll
            for (int nt = 0; nt < 4; nt++) {
                __stcs((float2*)(r0 + nt * 8), make_float2(acc[mt][nt][0], acc[mt][nt][1]));
                __stcs((float2*)(r1 + nt * 8), make_float2(acc[mt][nt][2], acc[mt][nt][3]));
            }
        }
    }
}

// ---------------- launch ----------------
extern "C" void kernel_launch(void* const* d_in, const int* in_sizes, int n_in,
                              void* d_out, int out_size) {
    const float* x  = (const float*)d_in[0];
    const float* w1 = (const float*)d_in[1];
    const float* b1 = (const float*)d_in[2];
    const float* ow = (const float*)d_in[3];
    const float* ob = (const float*)d_in[4];
    const float* dw = (const float*)d_in[5];
    float* out = (float*)d_out;

    k_conv1<<<(NB * HH * WW + 255) / 256, 256>>>(x, w1, b1);
    k_offset<<<NPOS / 256, 256>>>(ow, ob);

    cudaFuncSetAttribute(k_dcn, cudaFuncAttributeMaxDynamicSharedMemorySize, SM_TOTAL);
    k_dcn<<<2 * NSLICE, 256, SM_TOTAL>>>(dw, out);
}

// round 5
// speedup vs baseline: 3.3760x; 1.3901x over previous
#include <cuda_runtime.h>
#include <cuda_fp16.h>
#include <cstdint>

// Shapes (fixed):
//  input_tensor: (8, 3, 256, 256)   d_in[0]
//  conv1_w:      (8, 3, 1, 1)       d_in[1]
//  conv1_b:      (8,)               d_in[2]
//  offset_w:     (27, 8, 3, 3)      d_in[3]
//  offset_b:     (27,)              d_in[4]
//  dcn_w:        (512, 8, 3, 3)     d_in[5]
//  out:          (8, 512, 128, 128) float32

#define NB   8
#define HH   256
#define WW   256
#define HO   128
#define WO   128
#define NPOS (NB * HO * WO)      // 131072
#define TPOS 32                  // positions per tile
#define NT   (NPOS / TPOS)       // 4096 tiles
#define GRID 296

__device__ float g_y[NB * HH * WW * 8];     // [n][h][w][c] channels-last
__device__ float g_off[NB * 27 * HO * WO];  // [n][ch][sp]

// smem: W [512 ch][K=80 fp16], row stride 176 B (conflict-free ldmatrix);
//       A [32 pos][K=80 fp16], same stride.
#define RSTRIDE 176
#define SM_W 0
#define SM_A (512 * RSTRIDE)                  // 90112
#define SM_TOTAL (SM_A + TPOS * RSTRIDE)      // 95744

// ------------------------------------------------------------------ PTX utils
__device__ __forceinline__ uint32_t smem_u32(const void* p) {
    uint32_t a;
    asm("{ .reg .u64 t; cvta.to.shared.u64 t, %1; cvt.u32.u64 %0, t; }" : "=r"(a) : "l"(p));
    return a;
}
__device__ __forceinline__ void ldsm4(uint32_t* r, uint32_t a) {
    asm volatile("ldmatrix.sync.aligned.m8n8.x4.shared.b16 {%0,%1,%2,%3}, [%4];"
        : "=r"(r[0]), "=r"(r[1]), "=r"(r[2]), "=r"(r[3]) : "r"(a));
}
__device__ __forceinline__ void ldsm2(uint32_t* r, uint32_t a) {
    asm volatile("ldmatrix.sync.aligned.m8n8.x2.shared.b16 {%0,%1}, [%2];"
        : "=r"(r[0]), "=r"(r[1]) : "r"(a));
}
__device__ __forceinline__ void mma_f16(float* d, const uint32_t* a, const uint32_t* b) {
    asm volatile("mma.sync.aligned.m16n8k16.row.col.f32.f16.f16.f32 "
        "{%0,%1,%2,%3}, {%4,%5,%6,%7}, {%8,%9}, {%0,%1,%2,%3};"
        : "+f"(d[0]), "+f"(d[1]), "+f"(d[2]), "+f"(d[3])
        : "r"(a[0]), "r"(a[1]), "r"(a[2]), "r"(a[3]), "r"(b[0]), "r"(b[1]));
}

// ---------------- kernel 1: 1x1 conv (3->8) + leaky relu, channels-last ----------------
__global__ void k_conv1(const float* __restrict__ x,
                        const float* __restrict__ w1,
                        const float* __restrict__ b1) {
    int idx = blockIdx.x * blockDim.x + threadIdx.x;
    if (idx >= NB * HH * WW) return;
    int n  = idx >> 16;
    int hw = idx & 0xFFFF;
    float x0 = x[(n * 3 + 0) * 65536 + hw];
    float x1 = x[(n * 3 + 1) * 65536 + hw];
    float x2 = x[(n * 3 + 2) * 65536 + hw];
    float v[8];
#pragma unroll
    for (int c = 0; c < 8; c++) {
        float t = __ldg(&w1[c * 3 + 0]) * x0 + __ldg(&w1[c * 3 + 1]) * x1 +
                  __ldg(&w1[c * 3 + 2]) * x2 + __ldg(&b1[c]);
        v[c] = t >= 0.f ? t : 0.1f * t;
    }
    float4* o = (float4*)(g_y + (size_t)idx * 8);
    o[0] = make_float4(v[0], v[1], v[2], v[3]);
    o[1] = make_float4(v[4], v[5], v[6], v[7]);
}

// ---------------- kernel 2: 3x3 stride-2 conv (8->27) + bias; sigmoid on mask ----------
__global__ void k_offset(const float* __restrict__ ow, const float* __restrict__ ob) {
    __shared__ float ws[27 * 9 * 8];
    int tid = threadIdx.x;
    for (int i = tid; i < 1944; i += 256) {
        int oc = i / 72;
        int rem = i - oc * 72;
        int ic = rem / 9;
        int tap = rem - ic * 9;
        ws[(oc * 9 + tap) * 8 + ic] = ow[i];
    }
    __syncthreads();

    int idx = blockIdx.x * 256 + tid;
    int n = idx >> 14;
    int sp = idx & 16383;
    int ho = sp >> 7, wo = sp & 127;

    float acc[27];
#pragma unroll
    for (int c = 0; c < 27; c++) acc[c] = 0.f;

#pragma unroll 1
    for (int kh = 0; kh < 3; kh++) {
        int hy = 2 * ho - 1 + kh;
        if ((unsigned)hy >= HH) continue;
#pragma unroll 1
        for (int kw = 0; kw < 3; kw++) {
            int wx = 2 * wo - 1 + kw;
            if ((unsigned)wx >= WW) continue;
            const float4* yp = (const float4*)(g_y + ((size_t)((n * HH + hy) * WW + wx)) * 8);
            float4 u = yp[0], v = yp[1];
            int tap = kh * 3 + kw;
#pragma unroll
            for (int oc = 0; oc < 27; oc++) {
                const float4* wp = (const float4*)(ws + (oc * 9 + tap) * 8);
                float4 a = wp[0], b = wp[1];
                acc[oc] += u.x * a.x + u.y * a.y + u.z * a.z + u.w * a.w +
                           v.x * b.x + v.y * b.y + v.z * b.z + v.w * b.w;
            }
        }
    }

    float* op = g_off + (size_t)n * 27 * 16384 + sp;
#pragma unroll
    for (int c = 0; c < 27; c++) {
        float v = acc[c] + __ldg(&ob[c]);
        if (c >= 18) v = 1.f / (1.f + __expf(-v));
        op[c * 16384] = v;
    }
}

// ---------------- kernel 3: deformable sampling + HMMA fp16 GEMM -----------------------
// Grid 296 persistent. Per tile: M=512 ch x N=32 pos x K=80 (kk = tap*8+c, pad 72..79=0).
// Single fp16 term (no split). W resident [ch][kk]; samples [pos][kk]; stride 176B.
// 8 warps: warp tile 64 ch x 32 pos.

__global__ void __launch_bounds__(256, 2)
k_dcn(const float* __restrict__ dw, float* __restrict__ out) {
    extern __shared__ char smem[];
    uint32_t sb = smem_u32(smem);
    int tid = threadIdx.x, lane = tid & 31, wid = tid >> 5;

    // zero all smem (covers kk 72..79 pads and row tail pads)
    for (int i = tid; i < SM_TOTAL / 16; i += 256)
        ((uint4*)smem)[i] = make_uint4(0, 0, 0, 0);
    __syncthreads();

    // W fill: W[ch][kk] fp16, kk = tap*8 + c
    for (int i = tid; i < 512 * 72; i += 256) {
        int ch = i / 72, j = i - ch * 72;      // j = c*9 + tap
        int c = j / 9, k = j - c * 9;
        int kk = k * 8 + c;
        *(__half*)(smem + SM_W + ch * RSTRIDE + kk * 2) = __float2half_rn(dw[i]);
    }

    // per-lane ldmatrix bases
    // A-op (W, m16 rows): lanes 0-15 -> ch rows, lanes 16-31 -> +16B (k+8)
    uint32_t wa_base = sb + SM_W + (uint32_t)((wid * 64 + (lane & 15)) * RSTRIDE) +
                       ((lane >> 4) << 4);
    // B-op (samples, n8 cols): lanes 0-7 -> pos rows, lanes 8-15 -> +16B
    uint32_t ba_base = sb + SM_A + (uint32_t)((lane & 7) * RSTRIDE) +
                       (((lane >> 3) & 1) << 4);

    int g = lane >> 2, tg = lane & 3;

    for (int tile = blockIdx.x; tile < NT; tile += GRID) {
        int pbase = tile << 5;
        int n = pbase >> 14;
        int spbase = pbase & 16383;

        __syncthreads();   // previous tile's ldmatrix reads complete (W fill on iter 0)

        // ---- sampling: 32 pos x 9 taps = 288 tasks ----
        for (int t = tid; t < 288; t += 256) {
            int pos = t & 31;
            int k = t >> 5;                    // tap 0..8
            int sp = spbase + pos;
            int ho = sp >> 7, wo = sp & 127;
            const float* offp = g_off + (size_t)n * 27 * 16384 + sp;
            float dy = offp[(2 * k) * 16384];
            float dx = offp[(2 * k + 1) * 16384];
            float m  = offp[(18 + k) * 16384];
            int ky = k / 3, kx = k - ky * 3;
            float py = (float)(2 * ho - 1 + ky) + dy;
            float px = (float)(2 * wo - 1 + kx) + dx;
            float y0f = floorf(py), x0f = floorf(px);
            float fy = py - y0f, fx = px - x0f;
            int y0 = (int)y0f, x0 = (int)x0f;
            float wy0 = 1.f - fy, wx0 = 1.f - fx;

            float a[8] = {0, 0, 0, 0, 0, 0, 0, 0};
#pragma unroll
            for (int oy = 0; oy < 2; oy++) {
                int yy = y0 + oy;
                if ((unsigned)yy >= HH) continue;
                float wy = oy ? fy : wy0;
#pragma unroll
                for (int ox = 0; ox < 2; ox++) {
                    int xx = x0 + ox;
                    if ((unsigned)xx >= WW) continue;
                    float wgt = wy * (ox ? fx : wx0);
                    const float4* p =
                        (const float4*)(g_y + ((size_t)((n * HH + yy) * WW + xx)) * 8);
                    float4 u = p[0], v = p[1];
                    a[0] += wgt * u.x; a[1] += wgt * u.y; a[2] += wgt * u.z; a[3] += wgt * u.w;
                    a[4] += wgt * v.x; a[5] += wgt * v.y; a[6] += wgt * v.z; a[7] += wgt * v.w;
                }
            }
            uint32_t h4[4];
#pragma unroll
            for (int i = 0; i < 4; i++) {
                __half2 h = __floats2half2_rn(a[2 * i] * m, a[2 * i + 1] * m);
                h4[i] = *(uint32_t*)&h;
            }
            // A[pos][kk = k*8 .. k*8+7] : 16 bytes
            *(uint4*)(smem + SM_A + pos * RSTRIDE + k * 16) =
                make_uint4(h4[0], h4[1], h4[2], h4[3]);
        }
        __syncthreads();

        // ---- MMA: 64ch x 32pos per warp, K=80 ----
        float acc[4][4][4];
#pragma unroll
        for (int mt = 0; mt < 4; mt++)
#pragma unroll
            for (int nt = 0; nt < 4; nt++)
#pragma unroll
                for (int r = 0; r < 4; r++) acc[mt][nt][r] = 0.f;

#pragma unroll
        for (int ks = 0; ks < 5; ks++) {
            uint32_t af[4][4];
#pragma unroll
            for (int mt = 0; mt < 4; mt++)
                ldsm4(af[mt], wa_base + (uint32_t)(mt * 16 * RSTRIDE) + ks * 32);
#pragma unroll
            for (int nt = 0; nt < 4; nt++) {
                uint32_t bf[2];
                ldsm2(bf, ba_base + (uint32_t)(nt * 8 * RSTRIDE) + ks * 32);
#pragma unroll
                for (int mt = 0; mt < 4; mt++)
                    mma_f16(acc[mt][nt], af[mt], bf);
            }
        }

        // ---- epilogue: ch = wid*64 + mt*16 + g (+8), pos = nt*8 + 2*tg (+1) ----
#pragma unroll
        for (int mt = 0; mt < 4; mt++) {
            int ch0 = wid * 64 + mt * 16 + g;
            float* r0 = out + ((size_t)(n * 512 + ch0)) * 16384 + spbase + 2 * tg;
            float* r1 = r0 + (size_t)8 * 16384;
#pragma unroll
            for (int nt = 0; nt < 4; nt++) {
                __stcs((float2*)(r0 + nt * 8), make_float2(acc[mt][nt][0], acc[mt][nt][1]));
                __stcs((float2*)(r1 + nt * 8), make_float2(acc[mt][nt][2], acc[mt][nt][3]));
            }
        }
    }
}

// ---------------- launch ----------------
extern "C" void kernel_launch(void* const* d_in, const int* in_sizes, int n_in,
                              void* d_out, int out_size) {
    const float* x  = (const float*)d_in[0];
    const float* w1 = (const float*)d_in[1];
    const float* b1 = (const float*)d_in[2];
    const float* ow = (const float*)d_in[3];
    const float* ob = (const float*)d_in[4];
    const float* dw = (const float*)d_in[5];
    float* out = (float*)d_out;

    k_conv1<<<(NB * HH * WW + 255) / 256, 256>>>(x, w1, b1);
    k_offset<<<NPOS / 256, 256>>>(ow, ob);

    cudaFuncSetAttribute(k_dcn, cudaFuncAttributeMaxDynamicSharedMemorySize, SM_TOTAL);
    k_dcn<<<GRID, 256, SM_TOTAL>>>(dw, out);
}

// round 6
// speedup vs baseline: 4.0037x; 1.1859x over previous
#include <cuda_runtime.h>
#include <cuda_fp16.h>
#include <cstdint>

// Shapes (fixed):
//  input_tensor: (8, 3, 256, 256)   d_in[0]
//  conv1_w:      (8, 3, 1, 1)       d_in[1]
//  conv1_b:      (8,)               d_in[2]
//  offset_w:     (27, 8, 3, 3)      d_in[3]
//  offset_b:     (27,)              d_in[4]
//  dcn_w:        (512, 8, 3, 3)     d_in[5]
//  out:          (8, 512, 128, 128) float32

#define NB   8
#define HH   256
#define WW   256
#define HO   128
#define WO   128
#define NPOS (NB * HO * WO)      // 131072
#define TPOS 32
#define NT   (NPOS / TPOS)       // 4096
#define GRID 296

__device__ __half g_y[NB * HH * WW * 8];    // fp16 channels-last, 8 MB
__device__ float  g_off[NB * 27 * HO * WO]; // [n][ch][sp]

// smem: W [512 ch][K=80 fp16] stride 176 B (conflict-free ldmatrix);
//       A double buffer [32 pos][K=80 fp16] stride 176 B.
#define RSTRIDE 176
#define SM_W 0
#define SM_A (512 * RSTRIDE)                  // 90112
#define ABUF (TPOS * RSTRIDE)                 // 5632
#define SM_TOTAL (SM_A + 2 * ABUF)            // 101376

// ------------------------------------------------------------------ PTX utils
__device__ __forceinline__ uint32_t smem_u32(const void* p) {
    uint32_t a;
    asm("{ .reg .u64 t; cvta.to.shared.u64 t, %1; cvt.u32.u64 %0, t; }" : "=r"(a) : "l"(p));
    return a;
}
__device__ __forceinline__ void ldsm4(uint32_t* r, uint32_t a) {
    asm volatile("ldmatrix.sync.aligned.m8n8.x4.shared.b16 {%0,%1,%2,%3}, [%4];"
        : "=r"(r[0]), "=r"(r[1]), "=r"(r[2]), "=r"(r[3]) : "r"(a));
}
__device__ __forceinline__ void ldsm2(uint32_t* r, uint32_t a) {
    asm volatile("ldmatrix.sync.aligned.m8n8.x2.shared.b16 {%0,%1}, [%2];"
        : "=r"(r[0]), "=r"(r[1]) : "r"(a));
}
__device__ __forceinline__ void mma_f16(float* d, const uint32_t* a, const uint32_t* b) {
    asm volatile("mma.sync.aligned.m16n8k16.row.col.f32.f16.f16.f32 "
        "{%0,%1,%2,%3}, {%4,%5,%6,%7}, {%8,%9}, {%0,%1,%2,%3};"
        : "+f"(d[0]), "+f"(d[1]), "+f"(d[2]), "+f"(d[3])
        : "r"(a[0]), "r"(a[1]), "r"(a[2]), "r"(a[3]), "r"(b[0]), "r"(b[1]));
}
__device__ __forceinline__ float2 h2f(uint32_t h) {
    __half2 v = *(__half2*)&h;
    return __half22float2(v);
}

// ---------------- kernel 1: 1x1 conv (3->8) + leaky relu -> fp16 channels-last ---------
__global__ void k_conv1(const float* __restrict__ x,
                        const float* __restrict__ w1,
                        const float* __restrict__ b1) {
    int idx2 = blockIdx.x * blockDim.x + threadIdx.x;   // 2 px per thread
    if (idx2 >= NB * HH * WW / 2) return;
    int base = idx2 << 1;
    int n  = base >> 16;
    int hw = base & 0xFFFF;
    float2 c0 = *(const float2*)(x + (size_t)(n * 3 + 0) * 65536 + hw);
    float2 c1 = *(const float2*)(x + (size_t)(n * 3 + 1) * 65536 + hw);
    float2 c2 = *(const float2*)(x + (size_t)(n * 3 + 2) * 65536 + hw);
    float px0[2] = {c0.x, c0.y}, px1[2] = {c1.x, c1.y}, px2[2] = {c2.x, c2.y};
#pragma unroll
    for (int p = 0; p < 2; p++) {
        uint32_t h[4];
#pragma unroll
        for (int cp = 0; cp < 4; cp++) {
            float t0 = __ldg(&w1[(2 * cp) * 3 + 0]) * px0[p] +
                       __ldg(&w1[(2 * cp) * 3 + 1]) * px1[p] +
                       __ldg(&w1[(2 * cp) * 3 + 2]) * px2[p] + __ldg(&b1[2 * cp]);
            float t1 = __ldg(&w1[(2 * cp + 1) * 3 + 0]) * px0[p] +
                       __ldg(&w1[(2 * cp + 1) * 3 + 1]) * px1[p] +
                       __ldg(&w1[(2 * cp + 1) * 3 + 2]) * px2[p] + __ldg(&b1[2 * cp + 1]);
            t0 = t0 >= 0.f ? t0 : 0.1f * t0;
            t1 = t1 >= 0.f ? t1 : 0.1f * t1;
            __half2 hh = __floats2half2_rn(t0, t1);
            h[cp] = *(uint32_t*)&hh;
        }
        *(uint4*)(g_y + (size_t)(base + p) * 8) = make_uint4(h[0], h[1], h[2], h[3]);
    }
}

// ---------------- kernel 2: 3x3 stride-2 conv (8->27) + bias; sigmoid on mask ----------
__global__ void k_offset(const float* __restrict__ ow, const float* __restrict__ ob) {
    __shared__ float ws[27 * 9 * 8];
    int tid = threadIdx.x;
    for (int i = tid; i < 1944; i += 256) {
        int oc = i / 72;
        int rem = i - oc * 72;
        int ic = rem / 9;
        int tap = rem - ic * 9;
        ws[(oc * 9 + tap) * 8 + ic] = ow[i];
    }
    __syncthreads();

    int idx = blockIdx.x * 256 + tid;
    int n = idx >> 14;
    int sp = idx & 16383;
    int ho = sp >> 7, wo = sp & 127;

    float acc[27];
#pragma unroll
    for (int c = 0; c < 27; c++) acc[c] = 0.f;

#pragma unroll 1
    for (int kh = 0; kh < 3; kh++) {
        int hy = 2 * ho - 1 + kh;
        if ((unsigned)hy >= HH) continue;
#pragma unroll 1
        for (int kw = 0; kw < 3; kw++) {
            int wx = 2 * wo - 1 + kw;
            if ((unsigned)wx >= WW) continue;
            uint4 q = *(const uint4*)(g_y + ((size_t)((n * HH + hy) * WW + wx)) * 8);
            float2 f0 = h2f(q.x), f1 = h2f(q.y), f2 = h2f(q.z), f3 = h2f(q.w);
            float yv[8] = {f0.x, f0.y, f1.x, f1.y, f2.x, f2.y, f3.x, f3.y};
            int tap = kh * 3 + kw;
#pragma unroll
            for (int oc = 0; oc < 27; oc++) {
                const float* wp = ws + (oc * 9 + tap) * 8;
#pragma unroll
                for (int ic = 0; ic < 8; ic++) acc[oc] += yv[ic] * wp[ic];
            }
        }
    }

    float* op = g_off + (size_t)n * 27 * 16384 + sp;
#pragma unroll
    for (int c = 0; c < 27; c++) {
        float v = acc[c] + __ldg(&ob[c]);
        if (c >= 18) v = 1.f / (1.f + __expf(-v));
        op[c * 16384] = v;
    }
}

// ---------------- kernel 3: deformable sampling + HMMA fp16 GEMM (pipelined) -----------
// Per tile: M=512 ch x N=32 pos x K=80 (kk = tap*8+c, kk 72..79 zero pad).
// Double-buffered A, ONE sync per tile. Per iteration (tile t, sampling t+GRID):
//   offsets LDG -> MMA half (mt 0,1) + epilogue -> coords + gather LDG ->
//   MMA half (mt 2,3) + epilogue -> convert + STS -> sync.

struct SampTask {
    float dy, dx, m;
    uint4 q[4];
    float w[4];
};

__global__ void __launch_bounds__(256, 2)
k_dcn(const float* __restrict__ dw, float* __restrict__ out) {
    extern __shared__ char smem[];
    uint32_t sb = smem_u32(smem);
    int tid = threadIdx.x, lane = tid & 31, wid = tid >> 5;

    // zero smem (kk 72..79 pads stay zero forever)
    for (int i = tid; i < SM_TOTAL / 16; i += 256)
        ((uint4*)smem)[i] = make_uint4(0, 0, 0, 0);
    __syncthreads();

    // W fill: W[ch][kk] fp16, kk = tap*8 + c
    for (int i = tid; i < 512 * 72; i += 256) {
        int ch = i / 72, j = i - ch * 72;      // j = c*9 + tap
        int c = j / 9, k = j - c * 9;
        *(__half*)(smem + SM_W + ch * RSTRIDE + (k * 8 + c) * 2) = __float2half_rn(dw[i]);
    }

    uint32_t wa_base = sb + SM_W + (uint32_t)((wid * 64 + (lane & 15)) * RSTRIDE) +
                       ((lane >> 4) << 4);
    uint32_t ba_base0 = sb + SM_A + (uint32_t)((lane & 7) * RSTRIDE) +
                        (((lane >> 3) & 1) << 4);
    int g = lane >> 2, tg = lane & 3;

    int has2 = (tid < 32);

    // ---- prologue: fully sample first tile into buf 0 ----
    {
        int tile = blockIdx.x;
        int pbase = tile << 5;
        int n = pbase >> 14;
        int spbase = pbase & 16383;
        for (int t = tid; t < 288; t += 256) {
            int pos = t & 31, k = t >> 5;
            int sp = spbase + pos;
            int ho = sp >> 7, wo = sp & 127;
            const float* offp = g_off + (size_t)n * 27 * 16384 + sp;
            float dy = offp[(2 * k) * 16384];
            float dx = offp[(2 * k + 1) * 16384];
            float m  = offp[(18 + k) * 16384];
            int ky = k / 3, kx = k - ky * 3;
            float py = (float)(2 * ho - 1 + ky) + dy;
            float px = (float)(2 * wo - 1 + kx) + dx;
            float y0f = floorf(py), x0f = floorf(px);
            float fy = py - y0f, fx = px - x0f;
            int y0 = (int)y0f, x0 = (int)x0f;
            float a[8] = {0, 0, 0, 0, 0, 0, 0, 0};
#pragma unroll
            for (int oy = 0; oy < 2; oy++) {
                int yy = y0 + oy;
                float wy = (oy ? fy : 1.f - fy) * ((unsigned)yy < HH ? 1.f : 0.f);
                int yc = min(max(yy, 0), HH - 1);
#pragma unroll
                for (int ox = 0; ox < 2; ox++) {
                    int xx = x0 + ox;
                    float wgt = wy * (ox ? fx : 1.f - fx) * ((unsigned)xx < WW ? 1.f : 0.f);
                    int xc = min(max(xx, 0), WW - 1);
                    uint4 q = *(const uint4*)(g_y + ((size_t)((n * HH + yc) * WW + xc)) * 8);
                    float2 f0 = h2f(q.x), f1 = h2f(q.y), f2 = h2f(q.z), f3 = h2f(q.w);
                    a[0] += wgt * f0.x; a[1] += wgt * f0.y; a[2] += wgt * f1.x; a[3] += wgt * f1.y;
                    a[4] += wgt * f2.x; a[5] += wgt * f2.y; a[6] += wgt * f3.x; a[7] += wgt * f3.y;
                }
            }
            uint32_t h4[4];
#pragma unroll
            for (int i = 0; i < 4; i++) {
                __half2 h = __floats2half2_rn(a[2 * i] * m, a[2 * i + 1] * m);
                h4[i] = *(uint32_t*)&h;
            }
            *(uint4*)(smem + SM_A + pos * RSTRIDE + k * 16) = make_uint4(h4[0], h4[1], h4[2], h4[3]);
        }
    }
    __syncthreads();

    int cur = 0;
    for (int tile = blockIdx.x; tile < NT; tile += GRID) {
        int pbase = tile << 5;
        int n = pbase >> 14;
        int spbase = pbase & 16383;

        int tn = tile + GRID;
        bool do_s = (tn < NT);
        int pbn = tn << 5;
        int n2 = pbn >> 14;
        int spbn = pbn & 16383;

        SampTask st[2];
        // ---- phase A: offset loads for next tile ----
        if (do_s) {
#pragma unroll
            for (int u = 0; u < 2; u++) {
                if (u && !has2) break;
                int t = tid + u * 256;
                int pos = t & 31, k = t >> 5;
                const float* offp = g_off + (size_t)n2 * 27 * 16384 + (spbn + pos);
                st[u].dy = offp[(2 * k) * 16384];
                st[u].dx = offp[(2 * k + 1) * 16384];
                st[u].m  = offp[(18 + k) * 16384];
            }
        }

        uint32_t ba_base = ba_base0 + (uint32_t)(cur * ABUF);

        // ---- MMA half 0 (mt 0,1) ----
        {
            float acc[2][4][4];
#pragma unroll
            for (int i = 0; i < 2; i++)
#pragma unroll
                for (int nt = 0; nt < 4; nt++)
#pragma unroll
                    for (int r = 0; r < 4; r++) acc[i][nt][r] = 0.f;
#pragma unroll
            for (int ks = 0; ks < 5; ks++) {
                uint32_t a0[4], a1[4];
                ldsm4(a0, wa_base + ks * 32);
                ldsm4(a1, wa_base + (uint32_t)(16 * RSTRIDE) + ks * 32);
#pragma unroll
                for (int nt = 0; nt < 4; nt++) {
                    uint32_t bf[2];
                    ldsm2(bf, ba_base + (uint32_t)(nt * 8 * RSTRIDE) + ks * 32);
                    mma_f16(acc[0][nt], a0, bf);
                    mma_f16(acc[1][nt], a1, bf);
                }
            }
#pragma unroll
            for (int i = 0; i < 2; i++) {
                int ch0 = wid * 64 + i * 16 + g;
                float* r0 = out + ((size_t)(n * 512 + ch0)) * 16384 + spbase + 2 * tg;
                float* r1 = r0 + (size_t)8 * 16384;
#pragma unroll
                for (int nt = 0; nt < 4; nt++) {
                    __stcs((float2*)(r0 + nt * 8), make_float2(acc[i][nt][0], acc[i][nt][1]));
                    __stcs((float2*)(r1 + nt * 8), make_float2(acc[i][nt][2], acc[i][nt][3]));
                }
            }
        }

        // ---- phase C: coords + gather loads for next tile ----
        if (do_s) {
#pragma unroll
            for (int u = 0; u < 2; u++) {
                if (u && !has2) break;
                int t = tid + u * 256;
                int pos = t & 31, k = t >> 5;
                int sp = spbn + pos;
                int ho = sp >> 7, wo = sp & 127;
                int ky = k / 3, kx = k - ky * 3;
                float py = (float)(2 * ho - 1 + ky) + st[u].dy;
                float px = (float)(2 * wo - 1 + kx) + st[u].dx;
                float y0f = floorf(py), x0f = floorf(px);
                float fy = py - y0f, fx = px - x0f;
                int y0 = (int)y0f, x0 = (int)x0f;
#pragma unroll
                for (int oy = 0; oy < 2; oy++) {
                    int yy = y0 + oy;
                    float wy = (oy ? fy : 1.f - fy) * ((unsigned)yy < HH ? 1.f : 0.f);
                    int yc = min(max(yy, 0), HH - 1);
#pragma unroll
                    for (int ox = 0; ox < 2; ox++) {
                        int xx = x0 + ox;
                        float wgt = wy * (ox ? fx : 1.f - fx) * ((unsigned)xx < WW ? 1.f : 0.f);
                        int xc = min(max(xx, 0), WW - 1);
                        st[u].w[oy * 2 + ox] = wgt;
                        st[u].q[oy * 2 + ox] =
                            *(const uint4*)(g_y + ((size_t)((n2 * HH + yc) * WW + xc)) * 8);
                    }
                }
            }
        }

        // ---- MMA half 1 (mt 2,3) ----
        {
            float acc[2][4][4];
#pragma unroll
            for (int i = 0; i < 2; i++)
#pragma unroll
                for (int nt = 0; nt < 4; nt++)
#pragma unroll
                    for (int r = 0; r < 4; r++) acc[i][nt][r] = 0.f;
#pragma unroll
            for (int ks = 0; ks < 5; ks++) {
                uint32_t a0[4], a1[4];
                ldsm4(a0, wa_base + (uint32_t)(32 * RSTRIDE) + ks * 32);
                ldsm4(a1, wa_base + (uint32_t)(48 * RSTRIDE) + ks * 32);
#pragma unroll
                for (int nt = 0; nt < 4; nt++) {
                    uint32_t bf[2];
                    ldsm2(bf, ba_base + (uint32_t)(nt * 8 * RSTRIDE) + ks * 32);
                    mma_f16(acc[0][nt], a0, bf);
                    mma_f16(acc[1][nt], a1, bf);
                }
            }
#pragma unroll
            for (int i = 0; i < 2; i++) {
                int ch0 = wid * 64 + (2 + i) * 16 + g;
                float* r0 = out + ((size_t)(n * 512 + ch0)) * 16384 + spbase + 2 * tg;
                float* r1 = r0 + (size_t)8 * 16384;
#pragma unroll
                for (int nt = 0; nt < 4; nt++) {
                    __stcs((float2*)(r0 + nt * 8), make_float2(acc[i][nt][0], acc[i][nt][1]));
                    __stcs((float2*)(r1 + nt * 8), make_float2(acc[i][nt][2], acc[i][nt][3]));
                }
            }
        }

        // ---- phase E: convert + STS into the other buffer ----
        if (do_s) {
            char* bufn = smem + SM_A + (cur ^ 1) * ABUF;
#pragma unroll
            for (int u = 0; u < 2; u++) {
                if (u && !has2) break;
                int t = tid + u * 256;
                int pos = t & 31, k = t >> 5;
                float a[8] = {0, 0, 0, 0, 0, 0, 0, 0};
#pragma unroll
                for (int cor = 0; cor < 4; cor++) {
                    float wgt = st[u].w[cor];
                    uint4 q = st[u].q[cor];
                    float2 f0 = h2f(q.x), f1 = h2f(q.y), f2 = h2f(q.z), f3 = h2f(q.w);
                    a[0] += wgt * f0.x; a[1] += wgt * f0.y; a[2] += wgt * f1.x; a[3] += wgt * f1.y;
                    a[4] += wgt * f2.x; a[5] += wgt * f2.y; a[6] += wgt * f3.x; a[7] += wgt * f3.y;
                }
                uint32_t h4[4];
#pragma unroll
                for (int i = 0; i < 4; i++) {
                    __half2 h = __floats2half2_rn(a[2 * i] * st[u].m, a[2 * i + 1] * st[u].m);
                    h4[i] = *(uint32_t*)&h;
                }
                *(uint4*)(bufn + pos * RSTRIDE + k * 16) = make_uint4(h4[0], h4[1], h4[2], h4[3]);
            }
        }

        __syncthreads();
        cur ^= 1;
    }
}

// ---------------- launch ----------------
extern "C" void kernel_launch(void* const* d_in, const int* in_sizes, int n_in,
                              void* d_out, int out_size) {
    const float* x  = (const float*)d_in[0];
    const float* w1 = (const float*)d_in[1];
    const float* b1 = (const float*)d_in[2];
    const float* ow = (const float*)d_in[3];
    const float* ob = (const float*)d_in[4];
    const float* dw = (const float*)d_in[5];
    float* out = (float*)d_out;

    k_conv1<<<(NB * HH * WW / 2 + 255) / 256, 256>>>(x, w1, b1);
    k_offset<<<NPOS / 256, 256>>>(ow, ob);

    cudaFuncSetAttribute(k_dcn, cudaFuncAttributeMaxDynamicSharedMemorySize, SM_TOTAL);
    k_dcn<<<GRID, 256, SM_TOTAL>>>(dw, out);
}

// round 7
// speedup vs baseline: 4.2502x; 1.0616x over previous
#include <cuda_runtime.h>
#include <cuda_fp16.h>
#include <cstdint>

// Shapes (fixed):
//  input_tensor: (8, 3, 256, 256)   d_in[0]
//  conv1_w:      (8, 3, 1, 1)       d_in[1]
//  conv1_b:      (8,)               d_in[2]
//  offset_w:     (27, 8, 3, 3)      d_in[3]
//  offset_b:     (27,)              d_in[4]
//  dcn_w:        (512, 8, 3, 3)     d_in[5]
//  out:          (8, 512, 128, 128) float32

#define NB   8
#define HH   256
#define WW   256
#define HO   128
#define WO   128
#define NPOS (NB * HO * WO)      // 131072
#define TPOS 32
#define NT   (NPOS / TPOS)       // 4096
#define GRID 296

__device__ __half g_y[NB * HH * WW * 8];    // fp16 channels-last, 8 MB

// smem layout (bytes), K=72 rows of 144 B (36 words: conflict-free ldmatrix)
#define RSTRIDE 144
#define SM_W    0                 // W [512][72] fp16            73728
#define SM_A    73728             // A double buf [32][72] fp16  2*4608
#define ABUF    4608
#define SM_YT   82944             // y strip [3][66] uint4       3168
#define SM_WS   86112             // wpk [9k][9tap][8ic][3] f32  7776
#define SM_BIAS 93888             // offset bias 27 f32          108
#define SM_TOTAL 94208

// ------------------------------------------------------------------ PTX utils
__device__ __forceinline__ uint32_t smem_u32(const void* p) {
    uint32_t a;
    asm("{ .reg .u64 t; cvta.to.shared.u64 t, %1; cvt.u32.u64 %0, t; }" : "=r"(a) : "l"(p));
    return a;
}
__device__ __forceinline__ void ldsm4(uint32_t* r, uint32_t a) {
    asm volatile("ldmatrix.sync.aligned.m8n8.x4.shared.b16 {%0,%1,%2,%3}, [%4];"
        : "=r"(r[0]), "=r"(r[1]), "=r"(r[2]), "=r"(r[3]) : "r"(a));
}
__device__ __forceinline__ void ldsm2(uint32_t* r, uint32_t a) {
    asm volatile("ldmatrix.sync.aligned.m8n8.x2.shared.b16 {%0,%1}, [%2];"
        : "=r"(r[0]), "=r"(r[1]) : "r"(a));
}
__device__ __forceinline__ uint32_t ldsm1(uint32_t a) {
    uint32_t r;
    asm volatile("ldmatrix.sync.aligned.m8n8.x1.shared.b16 {%0}, [%1];"
        : "=r"(r) : "r"(a));
    return r;
}
__device__ __forceinline__ void mma_f16(float* d, const uint32_t* a, const uint32_t* b) {
    asm volatile("mma.sync.aligned.m16n8k16.row.col.f32.f16.f16.f32 "
        "{%0,%1,%2,%3}, {%4,%5,%6,%7}, {%8,%9}, {%0,%1,%2,%3};"
        : "+f"(d[0]), "+f"(d[1]), "+f"(d[2]), "+f"(d[3])
        : "r"(a[0]), "r"(a[1]), "r"(a[2]), "r"(a[3]), "r"(b[0]), "r"(b[1]));
}
__device__ __forceinline__ void mma_f16_k8(float* d, const uint32_t* a, uint32_t b) {
    asm volatile("mma.sync.aligned.m16n8k8.row.col.f32.f16.f16.f32 "
        "{%0,%1,%2,%3}, {%4,%5}, {%6}, {%0,%1,%2,%3};"
        : "+f"(d[0]), "+f"(d[1]), "+f"(d[2]), "+f"(d[3])
        : "r"(a[0]), "r"(a[1]), "r"(b));
}
__device__ __forceinline__ float2 h2f(uint32_t h) {
    __half2 v = *(__half2*)&h;
    return __half22float2(v);
}

// ---------------- kernel 1: 1x1 conv (3->8) + leaky relu -> fp16 channels-last ---------
__global__ void k_conv1(const float* __restrict__ x,
                        const float* __restrict__ w1,
                        const float* __restrict__ b1) {
    int idx2 = blockIdx.x * blockDim.x + threadIdx.x;   // 2 px per thread
    if (idx2 >= NB * HH * WW / 2) return;
    int base = idx2 << 1;
    int n  = base >> 16;
    int hw = base & 0xFFFF;
    float2 c0 = *(const float2*)(x + (size_t)(n * 3 + 0) * 65536 + hw);
    float2 c1 = *(const float2*)(x + (size_t)(n * 3 + 1) * 65536 + hw);
    float2 c2 = *(const float2*)(x + (size_t)(n * 3 + 2) * 65536 + hw);
    float px0[2] = {c0.x, c0.y}, px1[2] = {c1.x, c1.y}, px2[2] = {c2.x, c2.y};
#pragma unroll
    for (int p = 0; p < 2; p++) {
        uint32_t h[4];
#pragma unroll
        for (int cp = 0; cp < 4; cp++) {
            float t0 = __ldg(&w1[(2 * cp) * 3 + 0]) * px0[p] +
                       __ldg(&w1[(2 * cp) * 3 + 1]) * px1[p] +
                       __ldg(&w1[(2 * cp) * 3 + 2]) * px2[p] + __ldg(&b1[2 * cp]);
            float t1 = __ldg(&w1[(2 * cp + 1) * 3 + 0]) * px0[p] +
                       __ldg(&w1[(2 * cp + 1) * 3 + 1]) * px1[p] +
                       __ldg(&w1[(2 * cp + 1) * 3 + 2]) * px2[p] + __ldg(&b1[2 * cp + 1]);
            t0 = t0 >= 0.f ? t0 : 0.1f * t0;
            t1 = t1 >= 0.f ? t1 : 0.1f * t1;
            __half2 hh = __floats2half2_rn(t0, t1);
            h[cp] = *(uint32_t*)&hh;
        }
        *(uint4*)(g_y + (size_t)(base + p) * 8) = make_uint4(h[0], h[1], h[2], h[3]);
    }
}

// ---------------- kernel 2: fused offset-conv + deformable sampling + HMMA GEMM --------
// Per tile: M=512 ch x N=32 pos x K=72 (kk = tap*8+c). 4x k16 MMA + 1x k8 tail.
// Offset conv (3x3 s2, 8->27) computed per tile from a cooperatively staged 3x66
// y-strip: tile positions share one output row, so the receptive field is tiny.

// offset conv evaluation for (pos, k): returns (dy, dx, mask_raw)
__device__ __forceinline__ float3 om_eval(int pos, int k, const char* ytile,
                                          const float* wpk, const float* bias) {
    float dy = bias[2 * k], dx = bias[2 * k + 1], mm = bias[18 + k];
    const float* wp = wpk + k * 216;
#pragma unroll
    for (int tp = 0; tp < 9; tp++) {
        uint4 q = *(const uint4*)(ytile + ((tp / 3) * 66 + 2 * pos + (tp % 3)) * 16);
        float2 f0 = h2f(q.x), f1 = h2f(q.y), f2 = h2f(q.z), f3 = h2f(q.w);
        float yv[8] = {f0.x, f0.y, f1.x, f1.y, f2.x, f2.y, f3.x, f3.y};
        const float* w3 = wp + tp * 24;
#pragma unroll
        for (int ic = 0; ic < 8; ic++) {
            dy += yv[ic] * w3[ic * 3 + 0];
            dx += yv[ic] * w3[ic * 3 + 1];
            mm += yv[ic] * w3[ic * 3 + 2];
        }
    }
    return make_float3(dy, dx, mm);
}

struct SampTask {
    uint4 q[4];
    float w[4];
    float m;
};

__device__ __forceinline__ void mma_half(uint32_t wa, uint32_t ba, float acc[2][4][4]) {
#pragma unroll
    for (int ks = 0; ks < 4; ks++) {
        uint32_t a0[4], a1[4];
        ldsm4(a0, wa + ks * 32);
        ldsm4(a1, wa + (uint32_t)(16 * RSTRIDE) + ks * 32);
#pragma unroll
        for (int nt = 0; nt < 4; nt++) {
            uint32_t bf[2];
            ldsm2(bf, ba + (uint32_t)(nt * 8 * RSTRIDE) + ks * 32);
            mma_f16(acc[0][nt], a0, bf);
            mma_f16(acc[1][nt], a1, bf);
        }
    }
    // k8 tail (kk 64..71, byte offset 128)
    uint32_t a0t[2], a1t[2];
    ldsm2(a0t, wa + 128);
    ldsm2(a1t, wa + (uint32_t)(16 * RSTRIDE) + 128);
#pragma unroll
    for (int nt = 0; nt < 4; nt++) {
        uint32_t bt = ldsm1(ba + (uint32_t)(nt * 8 * RSTRIDE) + 128);
        mma_f16_k8(acc[0][nt], a0t, bt);
        mma_f16_k8(acc[1][nt], a1t, bt);
    }
}

__device__ __forceinline__ void epilogue_half(const float acc[2][4][4], float* out,
                                              int n, int spbase, int mh,
                                              int wid, int g, int tg) {
#pragma unroll
    for (int i = 0; i < 2; i++) {
        int ch0 = wid * 64 + (mh * 2 + i) * 16 + g;
        float* r0 = out + ((size_t)(n * 512 + ch0)) * 16384 + spbase + 2 * tg;
        float* r1 = r0 + (size_t)8 * 16384;
#pragma unroll
        for (int nt = 0; nt < 4; nt++) {
            __stcs((float2*)(r0 + nt * 8), make_float2(acc[i][nt][0], acc[i][nt][1]));
            __stcs((float2*)(r1 + nt * 8), make_float2(acc[i][nt][2], acc[i][nt][3]));
        }
    }
}

__global__ void __launch_bounds__(256, 2)
k_dcn(const float* __restrict__ dw,
      const float* __restrict__ ow, const float* __restrict__ ob,
      float* __restrict__ out) {
    extern __shared__ char smem[];
    uint32_t sb = smem_u32(smem);
    float* wpk  = (float*)(smem + SM_WS);
    float* bias = (float*)(smem + SM_BIAS);
    char*  ytile = smem + SM_YT;
    int tid = threadIdx.x, lane = tid & 31, wid = tid >> 5;

    // W fill: W[ch][kk] fp16, kk = tap*8 + c  (covers all 72 cols of every row)
    for (int i = tid; i < 512 * 72; i += 256) {
        int ch = i / 72, j = i - ch * 72;      // j = c*9 + tap
        int c = j / 9, k = j - c * 9;
        *(__half*)(smem + SM_W + ch * RSTRIDE + (k * 8 + c) * 2) = __float2half_rn(dw[i]);
    }
    // offset-conv weights, packed per k: wpk[k][tap][ic][{dy,dx,m}]
    for (int i = tid; i < 1944; i += 256) {
        int k = i / 216, r = i - k * 216;
        int t = r / 24, r2 = r - t * 24;
        int ic = r2 / 3, j = r2 - ic * 3;
        int oc = (j == 0) ? 2 * k : (j == 1) ? 2 * k + 1 : 18 + k;
        wpk[i] = ow[(oc * 8 + ic) * 9 + t];
    }
    if (tid < 27) bias[tid] = ob[tid];
    __syncthreads();

    uint32_t wa_base = sb + SM_W + (uint32_t)((wid * 64 + (lane & 15)) * RSTRIDE) +
                       ((lane >> 4) << 4);
    uint32_t ba_base0 = sb + SM_A + (uint32_t)((lane & 7) * RSTRIDE) +
                        (((lane >> 3) & 1) << 4);
    int g = lane >> 2, tg = lane & 3;
    int has2 = (tid < 32);

    // ---- prologue: fully sample first tile into buf 0 ----
    {
        int pb = blockIdx.x << 5;
        int n0 = pb >> 14;
        int sp0 = pb & 16383;
        int ho0 = sp0 >> 7, wo0 = sp0 & 127;
        if (tid < 198) {
            int r = tid / 66, c = tid - r * 66;
            int hy = 2 * ho0 - 1 + r, wx = 2 * wo0 - 1 + c;
            uint4 v = make_uint4(0, 0, 0, 0);
            if ((unsigned)hy < HH && (unsigned)wx < WW)
                v = *(const uint4*)(g_y + ((size_t)((n0 * HH + hy) * WW + wx)) * 8);
            *(uint4*)(ytile + tid * 16) = v;
        }
        __syncthreads();
#pragma unroll
        for (int u = 0; u < 2; u++) {
            if (u && !has2) break;
            int t = tid + u * 256;
            int pos = t & 31, k = t >> 5;
            float3 o = om_eval(pos, k, ytile, wpk, bias);
            float m = 1.f / (1.f + __expf(-o.z));
            int sp = sp0 + pos;
            int ho = sp >> 7, wo = sp & 127;
            int ky = k / 3, kx = k - ky * 3;
            float py = (float)(2 * ho - 1 + ky) + o.x;
            float px = (float)(2 * wo - 1 + kx) + o.y;
            float y0f = floorf(py), x0f = floorf(px);
            float fy = py - y0f, fx = px - x0f;
            int y0 = (int)y0f, x0 = (int)x0f;
            float a[8] = {0, 0, 0, 0, 0, 0, 0, 0};
#pragma unroll
            for (int oy = 0; oy < 2; oy++) {
                int yy = y0 + oy;
                float wy = (oy ? fy : 1.f - fy) * ((unsigned)yy < HH ? 1.f : 0.f);
                int yc = min(max(yy, 0), HH - 1);
#pragma unroll
                for (int ox = 0; ox < 2; ox++) {
                    int xx = x0 + ox;
                    float wgt = wy * (ox ? fx : 1.f - fx) * ((unsigned)xx < WW ? 1.f : 0.f);
                    int xc = min(max(xx, 0), WW - 1);
                    uint4 q = *(const uint4*)(g_y + ((size_t)((n0 * HH + yc) * WW + xc)) * 8);
                    float2 f0 = h2f(q.x), f1 = h2f(q.y), f2 = h2f(q.z), f3 = h2f(q.w);
                    a[0] += wgt * f0.x; a[1] += wgt * f0.y; a[2] += wgt * f1.x; a[3] += wgt * f1.y;
                    a[4] += wgt * f2.x; a[5] += wgt * f2.y; a[6] += wgt * f3.x; a[7] += wgt * f3.y;
                }
            }
            uint32_t h4[4];
#pragma unroll
            for (int i = 0; i < 4; i++) {
                __half2 h = __floats2half2_rn(a[2 * i] * m, a[2 * i + 1] * m);
                h4[i] = *(uint32_t*)&h;
            }
            *(uint4*)(smem + SM_A + pos * RSTRIDE + k * 16) = make_uint4(h4[0], h4[1], h4[2], h4[3]);
        }
    }
    __syncthreads();

    int cur = 0;
    for (int tile = blockIdx.x; tile < NT; tile += GRID) {
        int pbase = tile << 5;
        int n = pbase >> 14;
        int spbase = pbase & 16383;

        int tn = tile + GRID;
        bool do_s = (tn < NT);
        int pbn = tn << 5;
        int n2 = pbn >> 14;
        int spbn = pbn & 16383;
        int ho2 = spbn >> 7, wo2 = spbn & 127;

        // ---- phase A: issue y-strip loads for next tile ----
        uint4 yv = make_uint4(0, 0, 0, 0);
        if (do_s && tid < 198) {
            int r = tid / 66, c = tid - r * 66;
            int hy = 2 * ho2 - 1 + r, wx = 2 * wo2 - 1 + c;
            if ((unsigned)hy < HH && (unsigned)wx < WW)
                yv = *(const uint4*)(g_y + ((size_t)((n2 * HH + hy) * WW + wx)) * 8);
        }

        uint32_t ba_base = ba_base0 + (uint32_t)(cur * ABUF);

        // ---- MMA half 0 (mt 0,1) + epilogue ----
        {
            float acc[2][4][4];
#pragma unroll
            for (int i = 0; i < 2; i++)
#pragma unroll
                for (int nt = 0; nt < 4; nt++)
#pragma unroll
                    for (int r = 0; r < 4; r++) acc[i][nt][r] = 0.f;
            mma_half(wa_base, ba_base, acc);
            epilogue_half(acc, out, n, spbase, 0, wid, g, tg);
        }

        // ---- stage y-strip, make it visible ----
        if (do_s && tid < 198) *(uint4*)(ytile + tid * 16) = yv;
        __syncthreads();

        // ---- phase B: offset conv + coords + gather loads for next tile ----
        SampTask st[2];
        if (do_s) {
#pragma unroll
            for (int u = 0; u < 2; u++) {
                if (u && !has2) break;
                int t = tid + u * 256;
                int pos = t & 31, k = t >> 5;
                float3 o = om_eval(pos, k, ytile, wpk, bias);
                st[u].m = 1.f / (1.f + __expf(-o.z));
                int sp = spbn + pos;
                int ho = sp >> 7, wo = sp & 127;
                int ky = k / 3, kx = k - ky * 3;
                float py = (float)(2 * ho - 1 + ky) + o.x;
                float px = (float)(2 * wo - 1 + kx) + o.y;
                float y0f = floorf(py), x0f = floorf(px);
                float fy = py - y0f, fx = px - x0f;
                int y0 = (int)y0f, x0 = (int)x0f;
#pragma unroll
                for (int oy = 0; oy < 2; oy++) {
                    int yy = y0 + oy;
                    float wy = (oy ? fy : 1.f - fy) * ((unsigned)yy < HH ? 1.f : 0.f);
                    int yc = min(max(yy, 0), HH - 1);
#pragma unroll
                    for (int ox = 0; ox < 2; ox++) {
                        int xx = x0 + ox;
                        float wgt = wy * (ox ? fx : 1.f - fx) * ((unsigned)xx < WW ? 1.f : 0.f);
                        int xc = min(max(xx, 0), WW - 1);
                        st[u].w[oy * 2 + ox] = wgt;
                        st[u].q[oy * 2 + ox] =
                            *(const uint4*)(g_y + ((size_t)((n2 * HH + yc) * WW + xc)) * 8);
                    }
                }
            }
        }

        // ---- MMA half 1 (mt 2,3) + epilogue ----
        {
            float acc[2][4][4];
#pragma unroll
            for (int i = 0; i < 2; i++)
#pragma unroll
                for (int nt = 0; nt < 4; nt++)
#pragma unroll
                    for (int r = 0; r < 4; r++) acc[i][nt][r] = 0.f;
            mma_half(wa_base + (uint32_t)(32 * RSTRIDE), ba_base, acc);
            epilogue_half(acc, out, n, spbase, 1, wid, g, tg);
        }

        // ---- phase E: convert + STS into the other A buffer ----
        if (do_s) {
            char* bufn = smem + SM_A + (cur ^ 1) * ABUF;
#pragma unroll
            for (int u = 0; u < 2; u++) {
                if (u && !has2) break;
                int t = tid + u * 256;
                int pos = t & 31, k = t >> 5;
                float a[8] = {0, 0, 0, 0, 0, 0, 0, 0};
#pragma unroll
                for (int cor = 0; cor < 4; cor++) {
                    float wgt = st[u].w[cor];
                    uint4 q = st[u].q[cor];
                    float2 f0 = h2f(q.x), f1 = h2f(q.y), f2 = h2f(q.z), f3 = h2f(q.w);
                    a[0] += wgt * f0.x; a[1] += wgt * f0.y; a[2] += wgt * f1.x; a[3] += wgt * f1.y;
                    a[4] += wgt * f2.x; a[5] += wgt * f2.y; a[6] += wgt * f3.x; a[7] += wgt * f3.y;
                }
                uint32_t h4[4];
#pragma unroll
                for (int i = 0; i < 4; i++) {
                    __half2 h = __floats2half2_rn(a[2 * i] * st[u].m, a[2 * i + 1] * st[u].m);
                    h4[i] = *(uint32_t*)&h;
                }
                *(uint4*)(bufn + pos * RSTRIDE + k * 16) = make_uint4(h4[0], h4[1], h4[2], h4[3]);
            }
        }

        __syncthreads();
        cur ^= 1;
    }
}

// ---------------- launch ----------------
extern "C" void kernel_launch(void* const* d_in, const int* in_sizes, int n_in,
                              void* d_out, int out_size) {
    const float* x  = (const float*)d_in[0];
    const float* w1 = (const float*)d_in[1];
    const float* b1 = (const float*)d_in[2];
    const float* ow = (const float*)d_in[3];
    const float* ob = (const float*)d_in[4];
    const float* dw = (const float*)d_in[5];
    float* out = (float*)d_out;

    k_conv1<<<(NB * HH * WW / 2 + 255) / 256, 256>>>(x, w1, b1);

    cudaFuncSetAttribute(k_dcn, cudaFuncAttributeMaxDynamicSharedMemorySize, SM_TOTAL);
    k_dcn<<<GRID, 256, SM_TOTAL>>>(dw, ow, ob, out);
}

// round 8
// speedup vs baseline: 4.4424x; 1.0452x over previous
#include <cuda_runtime.h>
#include <cuda_fp16.h>
#include <cstdint>

// Shapes (fixed):
//  input_tensor: (8, 3, 256, 256)   d_in[0]
//  conv1_w:      (8, 3, 1, 1)       d_in[1]
//  conv1_b:      (8,)               d_in[2]
//  offset_w:     (27, 8, 3, 3)      d_in[3]
//  offset_b:     (27,)              d_in[4]
//  dcn_w:        (512, 8, 3, 3)     d_in[5]
//  out:          (8, 512, 128, 128) float32

#define NB   8
#define HH   256
#define WW   256
#define HO   128
#define WO   128
#define NPOS (NB * HO * WO)      // 131072
#define TPOS 64
#define NT   (NPOS / TPOS)       // 2048
#define GRID 296

typedef unsigned long long u64;

__device__ __half g_y[NB * HH * WW * 8];    // fp16 channels-last, 8 MB

// smem layout (bytes). K=72 rows of 144 B (36 words: conflict-free ldmatrix).
#define RSTRIDE 144
#define SM_W    0                       // W [512][72] fp16          73728
#define SM_A    73728                   // A double buf [64][72]     2*9216
#define ABUF    9216
#define SM_YE   92160                   // y strip even px [3][66]u4 3168
#define SM_YO   95328                   // y strip odd  px [3][66]u4 3168
#define SM_WS   98496                   // wpk [9k][9tap][8ic][3]    7776
#define SM_BIAS 106272                  // offset bias 27 f32        108
#define SM_TOTAL 106496

// ------------------------------------------------------------------ PTX utils
__device__ __forceinline__ uint32_t smem_u32(const void* p) {
    uint32_t a;
    asm("{ .reg .u64 t; cvta.to.shared.u64 t, %1; cvt.u32.u64 %0, t; }" : "=r"(a) : "l"(p));
    return a;
}
__device__ __forceinline__ void ldsm4(uint32_t* r, uint32_t a) {
    asm volatile("ldmatrix.sync.aligned.m8n8.x4.shared.b16 {%0,%1,%2,%3}, [%4];"
        : "=r"(r[0]), "=r"(r[1]), "=r"(r[2]), "=r"(r[3]) : "r"(a));
}
__device__ __forceinline__ void ldsm2(uint32_t* r, uint32_t a) {
    asm volatile("ldmatrix.sync.aligned.m8n8.x2.shared.b16 {%0,%1}, [%2];"
        : "=r"(r[0]), "=r"(r[1]) : "r"(a));
}
__device__ __forceinline__ uint32_t ldsm1(uint32_t a) {
    uint32_t r;
    asm volatile("ldmatrix.sync.aligned.m8n8.x1.shared.b16 {%0}, [%1];"
        : "=r"(r) : "r"(a));
    return r;
}
__device__ __forceinline__ void mma_f16(float* d, const uint32_t* a, const uint32_t* b) {
    asm volatile("mma.sync.aligned.m16n8k16.row.col.f32.f16.f16.f32 "
        "{%0,%1,%2,%3}, {%4,%5,%6,%7}, {%8,%9}, {%0,%1,%2,%3};"
        : "+f"(d[0]), "+f"(d[1]), "+f"(d[2]), "+f"(d[3])
        : "r"(a[0]), "r"(a[1]), "r"(a[2]), "r"(a[3]), "r"(b[0]), "r"(b[1]));
}
__device__ __forceinline__ void mma_f16_k8(float* d, const uint32_t* a, uint32_t b) {
    asm volatile("mma.sync.aligned.m16n8k8.row.col.f32.f16.f16.f32 "
        "{%0,%1,%2,%3}, {%4,%5}, {%6}, {%0,%1,%2,%3};"
        : "+f"(d[0]), "+f"(d[1]), "+f"(d[2]), "+f"(d[3])
        : "r"(a[0]), "r"(a[1]), "r"(b));
}
__device__ __forceinline__ float2 h2f(uint32_t h) {
    __half2 v = *(__half2*)&h;
    return __half22float2(v);
}

// ---------------- kernel 1: 1x1 conv (3->8) + leaky relu -> fp16 channels-last ---------
__global__ void k_conv1(const float* __restrict__ x,
                        const float* __restrict__ w1,
                        const float* __restrict__ b1) {
    int idx2 = blockIdx.x * blockDim.x + threadIdx.x;   // 2 px per thread
    if (idx2 >= NB * HH * WW / 2) return;
    int base = idx2 << 1;
    int n  = base >> 16;
    int hw = base & 0xFFFF;
    float2 c0 = *(const float2*)(x + (size_t)(n * 3 + 0) * 65536 + hw);
    float2 c1 = *(const float2*)(x + (size_t)(n * 3 + 1) * 65536 + hw);
    float2 c2 = *(const float2*)(x + (size_t)(n * 3 + 2) * 65536 + hw);
    float px0[2] = {c0.x, c0.y}, px1[2] = {c1.x, c1.y}, px2[2] = {c2.x, c2.y};
#pragma unroll
    for (int p = 0; p < 2; p++) {
        uint32_t h[4];
#pragma unroll
        for (int cp = 0; cp < 4; cp++) {
            float t0 = __ldg(&w1[(2 * cp) * 3 + 0]) * px0[p] +
                       __ldg(&w1[(2 * cp) * 3 + 1]) * px1[p] +
                       __ldg(&w1[(2 * cp) * 3 + 2]) * px2[p] + __ldg(&b1[2 * cp]);
            float t1 = __ldg(&w1[(2 * cp + 1) * 3 + 0]) * px0[p] +
                       __ldg(&w1[(2 * cp + 1) * 3 + 1]) * px1[p] +
                       __ldg(&w1[(2 * cp + 1) * 3 + 2]) * px2[p] + __ldg(&b1[2 * cp + 1]);
            t0 = t0 >= 0.f ? t0 : 0.1f * t0;
            t1 = t1 >= 0.f ? t1 : 0.1f * t1;
            __half2 hh = __floats2half2_rn(t0, t1);
            h[cp] = *(uint32_t*)&hh;
        }
        *(uint4*)(g_y + (size_t)(base + p) * 8) = make_uint4(h[0], h[1], h[2], h[3]);
    }
}

// ---------------- kernel 2: fused offset-conv + sampling + HMMA GEMM -------------------
// Per tile: M=512 ch x N=64 pos x K=72 (kk = tap*8+c). Two MMA halves (64ch x 64pos/warp).
// Offset conv from even/odd-split y strip (conflict-free LDS). Epilogue assembles
// float4 via shfl_xor -> STG.128 (half the L1 store wavefronts).

__device__ __forceinline__ float3 om_eval(int pos, int k, const char* smem,
                                          const float* wpk, const float* bias) {
    float dy = bias[2 * k], dx = bias[2 * k + 1], mm = bias[18 + k];
    const float* wp = wpk + k * 216;
#pragma unroll
    for (int rr = 0; rr < 3; rr++) {
#pragma unroll
        for (int c = 0; c < 3; c++) {
            const char* bp = smem + ((c & 1) ? SM_YO : SM_YE) +
                             (size_t)(rr * 66 + pos + (c >> 1)) * 16;
            uint4 q = *(const uint4*)bp;
            float2 f0 = h2f(q.x), f1 = h2f(q.y), f2 = h2f(q.z), f3 = h2f(q.w);
            float yv[8] = {f0.x, f0.y, f1.x, f1.y, f2.x, f2.y, f3.x, f3.y};
            const float* w3 = wp + (rr * 3 + c) * 24;
#pragma unroll
            for (int ic = 0; ic < 8; ic++) {
                dy += yv[ic] * w3[ic * 3 + 0];
                dx += yv[ic] * w3[ic * 3 + 1];
                mm += yv[ic] * w3[ic * 3 + 2];
            }
        }
    }
    return make_float3(dy, dx, mm);
}

__device__ __forceinline__ void mma_half(uint32_t wa, uint32_t ba, float acc[2][8][4]) {
#pragma unroll
    for (int ks = 0; ks < 4; ks++) {
        uint32_t a0[4], a1[4];
        ldsm4(a0, wa + ks * 32);
        ldsm4(a1, wa + (uint32_t)(16 * RSTRIDE) + ks * 32);
#pragma unroll
        for (int nt = 0; nt < 8; nt++) {
            uint32_t bf[2];
            ldsm2(bf, ba + (uint32_t)(nt * 8 * RSTRIDE) + ks * 32);
            mma_f16(acc[0][nt], a0, bf);
            mma_f16(acc[1][nt], a1, bf);
        }
    }
    uint32_t a0t[2], a1t[2];
    ldsm2(a0t, wa + 128);
    ldsm2(a1t, wa + (uint32_t)(16 * RSTRIDE) + 128);
#pragma unroll
    for (int nt = 0; nt < 8; nt++) {
        uint32_t bt = ldsm1(ba + (uint32_t)(nt * 8 * RSTRIDE) + 128);
        mma_f16_k8(acc[0][nt], a0t, bt);
        mma_f16_k8(acc[1][nt], a1t, bt);
    }
}

// epilogue slice for one i: 8 shfl + 8 STG.128
__device__ __forceinline__ void epi_part(const float acc[2][8][4], float* out,
                                         int n, int spbase, int mh, int i,
                                         int wid, int lane) {
    int g = lane >> 2, tg = lane & 3;
    int odd = tg & 1;
    int ch0 = wid * 64 + (mh * 2 + i) * 16 + g;
#pragma unroll
    for (int r = 0; r < 2; r++) {
        float* rowp = out + (size_t)(n * 512 + ch0 + 8 * r) * 16384 + spbase;
#pragma unroll
        for (int p = 0; p < 4; p++) {
            int nt0 = 2 * p, nt1 = 2 * p + 1;
            float a0x = acc[i][nt0][2 * r], a0y = acc[i][nt0][2 * r + 1];
            float a1x = acc[i][nt1][2 * r], a1y = acc[i][nt1][2 * r + 1];
            u64 send = odd
                ? (((u64)__float_as_uint(a0y) << 32) | __float_as_uint(a0x))
                : (((u64)__float_as_uint(a1y) << 32) | __float_as_uint(a1x));
            u64 recv = __shfl_xor_sync(0xffffffffu, send, 1);
            float rx = __uint_as_float((uint32_t)recv);
            float ry = __uint_as_float((uint32_t)(recv >> 32));
            float4 v = odd ? make_float4(rx, ry, a1x, a1y)
                           : make_float4(a0x, a0y, rx, ry);
            int col = (odd ? nt1 : nt0) * 8 + (tg >> 1) * 4;
            __stcs((float4*)(rowp + col), v);
        }
    }
}

__global__ void __launch_bounds__(256, 2)
k_dcn(const float* __restrict__ dw,
      const float* __restrict__ ow, const float* __restrict__ ob,
      float* __restrict__ out) {
    extern __shared__ char smem[];
    uint32_t sb = smem_u32(smem);
    float* wpk  = (float*)(smem + SM_WS);
    float* bias = (float*)(smem + SM_BIAS);
    int tid = threadIdx.x, lane = tid & 31, wid = tid >> 5;

    // W fill: W[ch][kk] fp16, kk = tap*8 + c
    for (int i = tid; i < 512 * 72; i += 256) {
        int ch = i / 72, j = i - ch * 72;      // j = c*9 + tap
        int c = j / 9, k = j - c * 9;
        *(__half*)(smem + SM_W + ch * RSTRIDE + (k * 8 + c) * 2) = __float2half_rn(dw[i]);
    }
    // offset-conv weights packed per k: wpk[k][tap][ic][{dy,dx,m}]
    for (int i = tid; i < 1944; i += 256) {
        int k = i / 216, r = i - k * 216;
        int t = r / 24, r2 = r - t * 24;
        int ic = r2 / 3, j = r2 - ic * 3;
        int oc = (j == 0) ? 2 * k : (j == 1) ? 2 * k + 1 : 18 + k;
        wpk[i] = ow[(oc * 8 + ic) * 9 + t];
    }
    if (tid < 27) bias[tid] = ob[tid];

    uint32_t wa_base = sb + SM_W + (uint32_t)((wid * 64 + (lane & 15)) * RSTRIDE) +
                       ((lane >> 4) << 4);
    uint32_t ba_base0 = sb + SM_A + (uint32_t)((lane & 7) * RSTRIDE) +
                        (((lane >> 3) & 1) << 4);
    __syncthreads();

    // ---- prologue: fully sample first tile into buf 0 ----
    {
        int pb = blockIdx.x << 6;
        int n0 = pb >> 14;
        int sp0 = pb & 16383;
        int ho0 = sp0 >> 7, wo0 = sp0 & 127;
        for (int j = tid; j < 390; j += 256) {
            int rr = j / 130, p = j - rr * 130;
            int hy = 2 * ho0 - 1 + rr, wx = 2 * wo0 - 1 + p;
            uint4 v = make_uint4(0, 0, 0, 0);
            if ((unsigned)hy < HH && (unsigned)wx < WW)
                v = *(const uint4*)(g_y + ((size_t)((n0 * HH + hy) * WW + wx)) * 8);
            *(uint4*)(smem + ((p & 1) ? SM_YO : SM_YE) + (size_t)(rr * 66 + (p >> 1)) * 16) = v;
        }
        __syncthreads();
        for (int t = tid; t < 576; t += 256) {
            int pos = t & 63, k = t >> 6;
            float3 o = om_eval(pos, k, smem, wpk, bias);
            float m = 1.f / (1.f + __expf(-o.z));
            int sp = sp0 + pos;
            int ho = sp >> 7, wo = sp & 127;
            int ky = k / 3, kx = k - ky * 3;
            float py = (float)(2 * ho - 1 + ky) + o.x;
            float px = (float)(2 * wo - 1 + kx) + o.y;
            float y0f = floorf(py), x0f = floorf(px);
            float fy = py - y0f, fx = px - x0f;
            int y0 = (int)y0f, x0 = (int)x0f;
            float a[8] = {0, 0, 0, 0, 0, 0, 0, 0};
#pragma unroll
            for (int oy = 0; oy < 2; oy++) {
                int yy = y0 + oy;
                float wy = (oy ? fy : 1.f - fy) * ((unsigned)yy < HH ? 1.f : 0.f);
                int yc = min(max(yy, 0), HH - 1);
#pragma unroll
                for (int ox = 0; ox < 2; ox++) {
                    int xx = x0 + ox;
                    float wgt = wy * (ox ? fx : 1.f - fx) * ((unsigned)xx < WW ? 1.f : 0.f);
                    int xc = min(max(xx, 0), WW - 1);
                    uint4 q = *(const uint4*)(g_y + ((size_t)((n0 * HH + yc) * WW + xc)) * 8);
                    float2 f0 = h2f(q.x), f1 = h2f(q.y), f2 = h2f(q.z), f3 = h2f(q.w);
                    a[0] += wgt * f0.x; a[1] += wgt * f0.y; a[2] += wgt * f1.x; a[3] += wgt * f1.y;
                    a[4] += wgt * f2.x; a[5] += wgt * f2.y; a[6] += wgt * f3.x; a[7] += wgt * f3.y;
                }
            }
            uint32_t h4[4];
#pragma unroll
            for (int i = 0; i < 4; i++) {
                __half2 h = __floats2half2_rn(a[2 * i] * m, a[2 * i + 1] * m);
                h4[i] = *(uint32_t*)&h;
            }
            *(uint4*)(smem + SM_A + pos * RSTRIDE + k * 16) = make_uint4(h4[0], h4[1], h4[2], h4[3]);
        }
    }
    __syncthreads();

    int cur = 0;
    for (int tile = blockIdx.x; tile < NT; tile += GRID) {
        int pbase = tile << 6;
        int n = pbase >> 14;
        int spbase = pbase & 16383;

        int tn = tile + GRID;
        bool do_s = (tn < NT);
        int pbn = tn << 6;
        int n2 = pbn >> 14;
        int spbn = pbn & 16383;
        int ho2 = spbn >> 7, wo2 = spbn & 127;

        // ---- issue y-strip loads for next tile ----
        uint4 yv0 = make_uint4(0, 0, 0, 0), yv1 = make_uint4(0, 0, 0, 0);
        if (do_s) {
            {
                int rr = tid / 130, p = tid - rr * 130;
                if (rr < 3) {
                    int hy = 2 * ho2 - 1 + rr, wx = 2 * wo2 - 1 + p;
                    if ((unsigned)hy < HH && (unsigned)wx < WW)
                        yv0 = *(const uint4*)(g_y + ((size_t)((n2 * HH + hy) * WW + wx)) * 8);
                }
            }
            if (tid < 134) {
                int j = tid + 256;
                int rr = j / 130, p = j - rr * 130;
                int hy = 2 * ho2 - 1 + rr, wx = 2 * wo2 - 1 + p;
                if ((unsigned)hy < HH && (unsigned)wx < WW)
                    yv1 = *(const uint4*)(g_y + ((size_t)((n2 * HH + hy) * WW + wx)) * 8);
            }
        }

        uint32_t ba_base = ba_base0 + (uint32_t)(cur * ABUF);
        char* bufn = smem + SM_A + (cur ^ 1) * ABUF;

        // ======== MMA half 0 (ch wid*64 + 0..31) ========
        float acc[2][8][4];
#pragma unroll
        for (int i = 0; i < 2; i++)
#pragma unroll
            for (int nt = 0; nt < 8; nt++)
#pragma unroll
                for (int r = 0; r < 4; r++) acc[i][nt][r] = 0.f;
        mma_half(wa_base, ba_base, acc);

        // stage strip, sync so ytile is visible
        if (do_s) {
            {
                int rr = tid / 130, p = tid - rr * 130;
                if (rr < 3)
                    *(uint4*)(smem + ((p & 1) ? SM_YO : SM_YE) +
                              (size_t)(rr * 66 + (p >> 1)) * 16) = yv0;
            }
            if (tid < 134) {
                int j = tid + 256;
                int rr = j / 130, p = j - rr * 130;
                *(uint4*)(smem + ((p & 1) ? SM_YO : SM_YE) +
                          (size_t)(rr * 66 + (p >> 1)) * 16) = yv1;
            }
        }
        __syncthreads();

        // ---- gap 1: sample tasks 0..287 interleaved with epilogue half0 ----
#pragma unroll
        for (int u = 0; u < 2; u++) {
            bool act = do_s && (u == 0 || tid < 32);
            int t = tid + u * 256;        // gap1 tasks: 0..287
            int pos = t & 63, k = t >> 6;
            uint4 q[4];
            float w4[4], m;
            if (act) {
                float3 o = om_eval(pos, k, smem, wpk, bias);
                m = 1.f / (1.f + __expf(-o.z));
                int sp = spbn + pos;
                int ho = sp >> 7, wo = sp & 127;
                int ky = k / 3, kx = k - ky * 3;
                float py = (float)(2 * ho - 1 + ky) + o.x;
                float px = (float)(2 * wo - 1 + kx) + o.y;
                float y0f = floorf(py), x0f = floorf(px);
                float fy = py - y0f, fx = px - x0f;
                int y0 = (int)y0f, x0 = (int)x0f;
#pragma unroll
                for (int oy = 0; oy < 2; oy++) {
                    int yy = y0 + oy;
                    float wy = (oy ? fy : 1.f - fy) * ((unsigned)yy < HH ? 1.f : 0.f);
                    int yc = min(max(yy, 0), HH - 1);
#pragma unroll
                    for (int ox = 0; ox < 2; ox++) {
                        int xx = x0 + ox;
                        float wgt = wy * (ox ? fx : 1.f - fx) * ((unsigned)xx < WW ? 1.f : 0.f);
                        int xc = min(max(xx, 0), WW - 1);
                        w4[oy * 2 + ox] = wgt;
                        q[oy * 2 + ox] =
                            *(const uint4*)(g_y + ((size_t)((n2 * HH + yc) * WW + xc)) * 8);
                    }
                }
            }
            epi_part(acc, out, n, spbase, 0, u, wid, lane);   // latency cover
            if (act) {
                float a[8] = {0, 0, 0, 0, 0, 0, 0, 0};
#pragma unroll
                for (int cor = 0; cor < 4; cor++) {
                    float wgt = w4[cor];
                    float2 f0 = h2f(q[cor].x), f1 = h2f(q[cor].y);
                    float2 f2 = h2f(q[cor].z), f3 = h2f(q[cor].w);
                    a[0] += wgt * f0.x; a[1] += wgt * f0.y; a[2] += wgt * f1.x; a[3] += wgt * f1.y;
                    a[4] += wgt * f2.x; a[5] += wgt * f2.y; a[6] += wgt * f3.x; a[7] += wgt * f3.y;
                }
                uint32_t h4[4];
#pragma unroll
                for (int i = 0; i < 4; i++) {
                    __half2 h = __floats2half2_rn(a[2 * i] * m, a[2 * i + 1] * m);
                    h4[i] = *(uint32_t*)&h;
                }
                *(uint4*)(bufn + pos * RSTRIDE + k * 16) = make_uint4(h4[0], h4[1], h4[2], h4[3]);
            }
        }

        // ======== MMA half 1 (ch wid*64 + 32..63) ========
#pragma unroll
        for (int i = 0; i < 2; i++)
#pragma unroll
            for (int nt = 0; nt < 8; nt++)
#pragma unroll
                for (int r = 0; r < 4; r++) acc[i][nt][r] = 0.f;
        mma_half(wa_base + (uint32_t)(32 * RSTRIDE), ba_base, acc);

        // ---- gap 2: sample tasks 288..575 interleaved with epilogue half1 ----
#pragma unroll
        for (int u = 0; u < 2; u++) {
            bool act = do_s && (u == 0 || tid < 32);
            int t = 288 + tid + u * 256;
            int pos = t & 63, k = t >> 6;
            uint4 q[4];
            float w4[4], m;
            if (act) {
                float3 o = om_eval(pos, k, smem, wpk, bias);
                m = 1.f / (1.f + __expf(-o.z));
                int sp = spbn + pos;
                int ho = sp >> 7, wo = sp & 127;
                int ky = k / 3, kx = k - ky * 3;
                float py = (float)(2 * ho - 1 + ky) + o.x;
                float px = (float)(2 * wo - 1 + kx) + o.y;
                float y0f = floorf(py), x0f = floorf(px);
                float fy = py - y0f, fx = px - x0f;
                int y0 = (int)y0f, x0 = (int)x0f;
#pragma unroll
                for (int oy = 0; oy < 2; oy++) {
                    int yy = y0 + oy;
                    float wy = (oy ? fy : 1.f - fy) * ((unsigned)yy < HH ? 1.f : 0.f);
                    int yc = min(max(yy, 0), HH - 1);
#pragma unroll
                    for (int ox = 0; ox < 2; ox++) {
                        int xx = x0 + ox;
                        float wgt = wy * (ox ? fx : 1.f - fx) * ((unsigned)xx < WW ? 1.f : 0.f);
                        int xc = min(max(xx, 0), WW - 1);
                        w4[oy * 2 + ox] = wgt;
                        q[oy * 2 + ox] =
                            *(const uint4*)(g_y + ((size_t)((n2 * HH + yc) * WW + xc)) * 8);
                    }
                }
            }
            epi_part(acc, out, n, spbase, 1, u, wid, lane);
            if (act) {
                float a[8] = {0, 0, 0, 0, 0, 0, 0, 0};
#pragma unroll
                for (int cor = 0; cor < 4; cor++) {
                    float wgt = w4[cor];
                    float2 f0 = h2f(q[cor].x), f1 = h2f(q[cor].y);
                    float2 f2 = h2f(q[cor].z), f3 = h2f(q[cor].w);
                    a[0] += wgt * f0.x; a[1] += wgt * f0.y; a[2] += wgt * f1.x; a[3] += wgt * f1.y;
                    a[4] += wgt * f2.x; a[5] += wgt * f2.y; a[6] += wgt * f3.x; a[7] += wgt * f3.y;
                }
                uint32_t h4[4];
#pragma unroll
                for (int i = 0; i < 4; i++) {
                    __half2 h = __floats2half2_rn(a[2 * i] * m, a[2 * i + 1] * m);
                    h4[i] = *(uint32_t*)&h;
                }
                *(uint4*)(bufn + pos * RSTRIDE + k * 16) = make_uint4(h4[0], h4[1], h4[2], h4[3]);
            }
        }

        __syncthreads();
        cur ^= 1;
    }
}

// ---------------- launch ----------------
extern "C" void kernel_launch(void* const* d_in, const int* in_sizes, int n_in,
                              void* d_out, int out_size) {
    const float* x  = (const float*)d_in[0];
    const float* w1 = (const float*)d_in[1];
    const float* b1 = (const float*)d_in[2];
    const float* ow = (const float*)d_in[3];
    const float* ob = (const float*)d_in[4];
    const float* dw = (const float*)d_in[5];
    float* out = (float*)d_out;

    k_conv1<<<(NB * HH * WW / 2 + 255) / 256, 256>>>(x, w1, b1);

    cudaFuncSetAttribute(k_dcn, cudaFuncAttributeMaxDynamicSharedMemorySize, SM_TOTAL);
    k_dcn<<<GRID, 256, SM_TOTAL>>>(dw, ow, ob, out);
}

// round 9
// speedup vs baseline: 5.2599x; 1.1840x over previous
#include <cuda_runtime.h>
#include <cuda_fp16.h>
#include <cstdint>

// Shapes (fixed):
//  input_tensor: (8, 3, 256, 256)   d_in[0]
//  conv1_w:      (8, 3, 1, 1)       d_in[1]
//  conv1_b:      (8,)               d_in[2]
//  offset_w:     (27, 8, 3, 3)      d_in[3]
//  offset_b:     (27,)              d_in[4]
//  dcn_w:        (512, 8, 3, 3)     d_in[5]
//  out:          (8, 512, 128, 128) float32

#define NB   8
#define HH   256
#define WW   256
#define HO   128
#define WO   128
#define NPOS (NB * HO * WO)      // 131072
#define TPOS 64
#define NT   (NPOS / TPOS)       // 2048
#define GRID 296

typedef unsigned long long u64;

__device__ __half g_y[NB * HH * WW * 8];    // fp16 channels-last, 8 MB

// smem layout (bytes). K=72 rows of 144 B (36 words: conflict-free ldmatrix).
#define RSTRIDE 144
#define SM_W    0                   // W [512][72] fp16              73728
#define SM_A    73728               // A double buf [64][72]         2*9216
#define ABUF    9216
#define SM_P    92160               // P patch [64 pos][72] fp16     9216
#define SM_WOM  101376              // W_om [32 oc][72] fp16         4608
#define SM_OMS  105984              // om_s [28 oc][68 pos] f32      7616
#define SM_BIAS 113600              // offset bias 27 f32 (pad 128)
#define SM_TOTAL 113728

// ------------------------------------------------------------------ PTX utils
__device__ __forceinline__ uint32_t smem_u32(const void* p) {
    uint32_t a;
    asm("{ .reg .u64 t; cvta.to.shared.u64 t, %1; cvt.u32.u64 %0, t; }" : "=r"(a) : "l"(p));
    return a;
}
__device__ __forceinline__ void ldsm4(uint32_t* r, uint32_t a) {
    asm volatile("ldmatrix.sync.aligned.m8n8.x4.shared.b16 {%0,%1,%2,%3}, [%4];"
        : "=r"(r[0]), "=r"(r[1]), "=r"(r[2]), "=r"(r[3]) : "r"(a));
}
__device__ __forceinline__ void ldsm2(uint32_t* r, uint32_t a) {
    asm volatile("ldmatrix.sync.aligned.m8n8.x2.shared.b16 {%0,%1}, [%2];"
        : "=r"(r[0]), "=r"(r[1]) : "r"(a));
}
__device__ __forceinline__ uint32_t ldsm1(uint32_t a) {
    uint32_t r;
    asm volatile("ldmatrix.sync.aligned.m8n8.x1.shared.b16 {%0}, [%1];"
        : "=r"(r) : "r"(a));
    return r;
}
__device__ __forceinline__ void mma_f16(float* d, const uint32_t* a, const uint32_t* b) {
    asm volatile("mma.sync.aligned.m16n8k16.row.col.f32.f16.f16.f32 "
        "{%0,%1,%2,%3}, {%4,%5,%6,%7}, {%8,%9}, {%0,%1,%2,%3};"
        : "+f"(d[0]), "+f"(d[1]), "+f"(d[2]), "+f"(d[3])
        : "r"(a[0]), "r"(a[1]), "r"(a[2]), "r"(a[3]), "r"(b[0]), "r"(b[1]));
}
__device__ __forceinline__ void mma_f16_k8(float* d, const uint32_t* a, uint32_t b) {
    asm volatile("mma.sync.aligned.m16n8k8.row.col.f32.f16.f16.f32 "
        "{%0,%1,%2,%3}, {%4,%5}, {%6}, {%0,%1,%2,%3};"
        : "+f"(d[0]), "+f"(d[1]), "+f"(d[2]), "+f"(d[3])
        : "r"(a[0]), "r"(a[1]), "r"(b));
}
__device__ __forceinline__ float2 h2f(uint32_t h) {
    __half2 v = *(__half2*)&h;
    return __half22float2(v);
}

// ---------------- kernel 1: 1x1 conv (3->8) + leaky relu -> fp16 channels-last ---------
__global__ void k_conv1(const float* __restrict__ x,
                        const float* __restrict__ w1,
                        const float* __restrict__ b1) {
    int idx2 = blockIdx.x * blockDim.x + threadIdx.x;   // 2 px per thread
    if (idx2 >= NB * HH * WW / 2) return;
    int base = idx2 << 1;
    int n  = base >> 16;
    int hw = base & 0xFFFF;
    float2 c0 = *(const float2*)(x + (size_t)(n * 3 + 0) * 65536 + hw);
    float2 c1 = *(const float2*)(x + (size_t)(n * 3 + 1) * 65536 + hw);
    float2 c2 = *(const float2*)(x + (size_t)(n * 3 + 2) * 65536 + hw);
    float px0[2] = {c0.x, c0.y}, px1[2] = {c1.x, c1.y}, px2[2] = {c2.x, c2.y};
#pragma unroll
    for (int p = 0; p < 2; p++) {
        uint32_t h[4];
#pragma unroll
        for (int cp = 0; cp < 4; cp++) {
            float t0 = __ldg(&w1[(2 * cp) * 3 + 0]) * px0[p] +
                       __ldg(&w1[(2 * cp) * 3 + 1]) * px1[p] +
                       __ldg(&w1[(2 * cp) * 3 + 2]) * px2[p] + __ldg(&b1[2 * cp]);
            float t1 = __ldg(&w1[(2 * cp + 1) * 3 + 0]) * px0[p] +
                       __ldg(&w1[(2 * cp + 1) * 3 + 1]) * px1[p] +
                       __ldg(&w1[(2 * cp + 1) * 3 + 2]) * px2[p] + __ldg(&b1[2 * cp + 1]);
            t0 = t0 >= 0.f ? t0 : 0.1f * t0;
            t1 = t1 >= 0.f ? t1 : 0.1f * t1;
            __half2 hh = __floats2half2_rn(t0, t1);
            h[cp] = *(uint32_t*)&hh;
        }
        *(uint4*)(g_y + (size_t)(base + p) * 8) = make_uint4(h[0], h[1], h[2], h[3]);
    }
}

// ---------------- kernel 2: fused offset-GEMM + sampling + HMMA GEMM -------------------
// Per tile: main GEMM M=512 ch x N=64 pos x K=72. Offset conv also as MMA:
// om[32oc][64pos] = W_om[32][72] x P[64][72], P rows = the 9 patch uint4 per pos.

__device__ __forceinline__ uint4 load_p(int n2, int spbn, int j) {
    int tap = j >> 6, pos = j & 63;
    int sp = spbn + pos;
    int ho = sp >> 7, wo = sp & 127;
    int hy = 2 * ho - 1 + tap / 3;
    int wx = 2 * wo - 1 + tap % 3;
    uint4 v = make_uint4(0, 0, 0, 0);
    if ((unsigned)hy < HH && (unsigned)wx < WW)
        v = *(const uint4*)(g_y + ((size_t)((n2 * HH + hy) * WW + wx)) * 8);
    return v;
}
__device__ __forceinline__ void sts_p(char* smem, int j, uint4 v) {
    int tap = j >> 6, pos = j & 63;
    *(uint4*)(smem + SM_P + pos * RSTRIDE + tap * 16) = v;
}

// om GEMM: every warp computes 32 oc x 8 pos, adds bias, sigmoid on mask, writes om_s.
__device__ __forceinline__ void om_gemm(uint32_t sb, char* smem, int wid, int lane) {
    int g = lane >> 2, tg = lane & 3;
    float aco[2][4] = {{0, 0, 0, 0}, {0, 0, 0, 0}};
    uint32_t wa = sb + SM_WOM + (uint32_t)((lane & 15) * RSTRIDE) + ((lane >> 4) << 4);
    uint32_t bp = sb + SM_P + (uint32_t)((wid * 8 + (lane & 7)) * RSTRIDE) +
                  (((lane >> 3) & 1) << 4);
#pragma unroll
    for (int ks = 0; ks < 4; ks++) {
        uint32_t a0[4], a1[4], bo[2];
        ldsm4(a0, wa + ks * 32);
        ldsm4(a1, wa + (uint32_t)(16 * RSTRIDE) + ks * 32);
        ldsm2(bo, bp + ks * 32);
        mma_f16(aco[0], a0, bo);
        mma_f16(aco[1], a1, bo);
    }
    uint32_t a0t[2], a1t[2];
    ldsm2(a0t, wa + 128);
    ldsm2(a1t, wa + (uint32_t)(16 * RSTRIDE) + 128);
    uint32_t bt = ldsm1(bp + 128);
    mma_f16_k8(aco[0], a0t, bt);
    mma_f16_k8(aco[1], a1t, bt);

    float* om_s = (float*)(smem + SM_OMS);
    const float* bias = (const float*)(smem + SM_BIAS);
#pragma unroll
    for (int mt = 0; mt < 2; mt++)
#pragma unroll
        for (int r = 0; r < 2; r++) {
            int oc = mt * 16 + g + 8 * r;
            if (oc < 27) {
#pragma unroll
                for (int c = 0; c < 2; c++) {
                    int pos = wid * 8 + 2 * tg + c;
                    float v = aco[mt][2 * r + c] + bias[oc];
                    if (oc >= 18) v = 1.f / (1.f + __expf(-v));
                    om_s[oc * 68 + pos] = v;
                }
            }
        }
}

__device__ __forceinline__ void mma_half(uint32_t wa, uint32_t ba4, uint32_t bat,
                                         float acc[2][8][4]) {
#pragma unroll
    for (int ks = 0; ks < 4; ks++) {
        uint32_t a0[4], a1[4];
        ldsm4(a0, wa + ks * 32);
        ldsm4(a1, wa + (uint32_t)(16 * RSTRIDE) + ks * 32);
#pragma unroll
        for (int p = 0; p < 4; p++) {
            uint32_t b4[4];
            ldsm4(b4, ba4 + (uint32_t)(p * 16 * RSTRIDE) + ks * 32);
            mma_f16(acc[0][2 * p],     a0, b4);
            mma_f16(acc[0][2 * p + 1], a0, b4 + 2);
            mma_f16(acc[1][2 * p],     a1, b4);
            mma_f16(acc[1][2 * p + 1], a1, b4 + 2);
        }
    }
    uint32_t a0t[2], a1t[2];
    ldsm2(a0t, wa + 128);
    ldsm2(a1t, wa + (uint32_t)(16 * RSTRIDE) + 128);
#pragma unroll
    for (int p = 0; p < 4; p++) {
        uint32_t bt[2];
        ldsm2(bt, bat + (uint32_t)(p * 16 * RSTRIDE) + 128);
        mma_f16_k8(acc[0][2 * p],     a0t, bt[0]);
        mma_f16_k8(acc[0][2 * p + 1], a0t, bt[1]);
        mma_f16_k8(acc[1][2 * p],     a1t, bt[0]);
        mma_f16_k8(acc[1][2 * p + 1], a1t, bt[1]);
    }
}

// epilogue slice: shfl-assembled STG.128
__device__ __forceinline__ void epi_part(const float acc[2][8][4], float* out,
                                         int n, int spbase, int mh, int i,
                                         int wid, int lane) {
    int g = lane >> 2, tg = lane & 3;
    int odd = tg & 1;
    int ch0 = wid * 64 + (mh * 2 + i) * 16 + g;
#pragma unroll
    for (int r = 0; r < 2; r++) {
        float* rowp = out + (size_t)(n * 512 + ch0 + 8 * r) * 16384 + spbase;
#pragma unroll
        for (int p = 0; p < 4; p++) {
            int nt0 = 2 * p, nt1 = 2 * p + 1;
            float a0x = acc[i][nt0][2 * r], a0y = acc[i][nt0][2 * r + 1];
            float a1x = acc[i][nt1][2 * r], a1y = acc[i][nt1][2 * r + 1];
            u64 send = odd
                ? (((u64)__float_as_uint(a0y) << 32) | __float_as_uint(a0x))
                : (((u64)__float_as_uint(a1y) << 32) | __float_as_uint(a1x));
            u64 recv = __shfl_xor_sync(0xffffffffu, send, 1);
            float rx = __uint_as_float((uint32_t)recv);
            float ry = __uint_as_float((uint32_t)(recv >> 32));
            float4 v = odd ? make_float4(rx, ry, a1x, a1y)
                           : make_float4(a0x, a0y, rx, ry);
            int col = (odd ? nt1 : nt0) * 8 + (tg >> 1) * 4;
            __stcs((float4*)(rowp + col), v);
        }
    }
}

// gather one (pos,k) task: read om_s, 4 bilinear LDGs, convert, STS into bufn
__device__ __forceinline__ void gather_ldg(const float* om_s, int n2, int spbn, int t,
                                           uint4 q[4], float w4[5]) {
    int pos = t & 63, k = t >> 6;
    float dy = om_s[(2 * k) * 68 + pos];
    float dx = om_s[(2 * k + 1) * 68 + pos];
    w4[4] = om_s[(18 + k) * 68 + pos];
    int sp = spbn + pos;
    int ho = sp >> 7, wo = sp & 127;
    int ky = k / 3, kx = k - ky * 3;
    float py = (float)(2 * ho - 1 + ky) + dy;
    float px = (float)(2 * wo - 1 + kx) + dx;
    float y0f = floorf(py), x0f = floorf(px);
    float fy = py - y0f, fx = px - x0f;
    int y0 = (int)y0f, x0 = (int)x0f;
#pragma unroll
    for (int oy = 0; oy < 2; oy++) {
        int yy = y0 + oy;
        float wy = (oy ? fy : 1.f - fy) * ((unsigned)yy < HH ? 1.f : 0.f);
        int yc = min(max(yy, 0), HH - 1);
#pragma unroll
        for (int ox = 0; ox < 2; ox++) {
            int xx = x0 + ox;
            float wgt = wy * (ox ? fx : 1.f - fx) * ((unsigned)xx < WW ? 1.f : 0.f);
            int xc = min(max(xx, 0), WW - 1);
            w4[oy * 2 + ox] = wgt;
            q[oy * 2 + ox] = *(const uint4*)(g_y + ((size_t)((n2 * HH + yc) * WW + xc)) * 8);
        }
    }
}
__device__ __forceinline__ void gather_fin(char* bufn, int t, const uint4 q[4],
                                           const float w4[5]) {
    int pos = t & 63, k = t >> 6;
    float a[8] = {0, 0, 0, 0, 0, 0, 0, 0};
#pragma unroll
    for (int cor = 0; cor < 4; cor++) {
        float wgt = w4[cor];
        float2 f0 = h2f(q[cor].x), f1 = h2f(q[cor].y);
        float2 f2 = h2f(q[cor].z), f3 = h2f(q[cor].w);
        a[0] += wgt * f0.x; a[1] += wgt * f0.y; a[2] += wgt * f1.x; a[3] += wgt * f1.y;
        a[4] += wgt * f2.x; a[5] += wgt * f2.y; a[6] += wgt * f3.x; a[7] += wgt * f3.y;
    }
    float m = w4[4];
    uint32_t h4[4];
#pragma unroll
    for (int i = 0; i < 4; i++) {
        __half2 h = __floats2half2_rn(a[2 * i] * m, a[2 * i + 1] * m);
        h4[i] = *(uint32_t*)&h;
    }
    *(uint4*)(bufn + pos * RSTRIDE + k * 16) = make_uint4(h4[0], h4[1], h4[2], h4[3]);
}

__global__ void __launch_bounds__(256, 2)
k_dcn(const float* __restrict__ dw,
      const float* __restrict__ ow, const float* __restrict__ ob,
      float* __restrict__ out) {
    extern __shared__ char smem[];
    uint32_t sb = smem_u32(smem);
    int tid = threadIdx.x, lane = tid & 31, wid = tid >> 5;

    // W fill: W[ch][kk] fp16, kk = tap*8 + c
    for (int i = tid; i < 512 * 72; i += 256) {
        int ch = i / 72, j = i - ch * 72;      // j = c*9 + tap
        int c = j / 9, k = j - c * 9;
        *(__half*)(smem + SM_W + ch * RSTRIDE + (k * 8 + c) * 2) = __float2half_rn(dw[i]);
    }
    // W_om: zero pad rows then fill [oc][kk = tap*8 + ic]
    for (int i = tid; i < 4608 / 16; i += 256)
        ((uint4*)(smem + SM_WOM))[i] = make_uint4(0, 0, 0, 0);
    __syncthreads();
    for (int i = tid; i < 27 * 72; i += 256) {
        int oc = i / 72, j = i - oc * 72;      // j = ic*9 + tap
        int ic = j / 9, tap = j - ic * 9;
        *(__half*)(smem + SM_WOM + oc * RSTRIDE + (tap * 8 + ic) * 2) = __float2half_rn(ow[i]);
    }
    if (tid < 27) ((float*)(smem + SM_BIAS))[tid] = ob[tid];

    uint32_t wa_base = sb + SM_W + (uint32_t)((wid * 64 + (lane & 15)) * RSTRIDE) +
                       ((lane >> 4) << 4);
    uint32_t ba4_base = sb + SM_A + (uint32_t)(((lane & 7) + ((lane >> 4) << 3)) * RSTRIDE) +
                        (((lane >> 3) & 1) << 4);
    uint32_t bat_base = sb + SM_A + (uint32_t)(((lane & 7) + (((lane >> 3) & 1) << 3)) * RSTRIDE);
    const float* om_s = (const float*)(smem + SM_OMS);

    // ---- prologue: build P(tile0), om GEMM, gathers -> A buf0 ----
    {
        int pb = blockIdx.x << 6;
        int n0 = pb >> 14, sp0 = pb & 16383;
        for (int j = tid; j < 576; j += 256)
            sts_p(smem, j, load_p(n0, sp0, j));
        __syncthreads();
        om_gemm(sb, smem, wid, lane);
        __syncthreads();
        for (int t = tid; t < 576; t += 256) {
            uint4 q[4]; float w4[5];
            gather_ldg(om_s, n0, sp0, t, q, w4);
            gather_fin(smem + SM_A, t, q, w4);
        }
    }
    __syncthreads();

    int cur = 0;
    for (int tile = blockIdx.x; tile < NT; tile += GRID) {
        int pbase = tile << 6;
        int n = pbase >> 14;
        int spbase = pbase & 16383;

        int tn = tile + GRID;
        bool do_s = (tn < NT);
        int pbn = tn << 6;
        int n2 = pbn >> 14;
        int spbn = pbn & 16383;

        // ---- issue P LDGs for next tile (staged in regs, covered by MMA half0) ----
        uint4 pv0 = make_uint4(0, 0, 0, 0), pv1 = pv0, pv2 = pv0;
        if (do_s) {
            if (tid < 64) pv2 = load_p(n2, spbn, tid + 512);
            pv0 = load_p(n2, spbn, tid);
            pv1 = load_p(n2, spbn, tid + 256);
        }

        uint32_t ba4 = ba4_base + (uint32_t)(cur * ABUF);
        uint32_t bat = bat_base + (uint32_t)(cur * ABUF);
        char* bufn = smem + SM_A + (cur ^ 1) * ABUF;

        // ======== MMA half 0 (ch wid*64 + 0..31) ========
        float acc[2][8][4];
#pragma unroll
        for (int i = 0; i < 2; i++)
#pragma unroll
            for (int nt = 0; nt < 8; nt++)
#pragma unroll
                for (int r = 0; r < 4; r++) acc[i][nt][r] = 0.f;
        mma_half(wa_base, ba4, bat, acc);

        if (do_s) {
            sts_p(smem, tid, pv0);
            sts_p(smem, tid + 256, pv1);
            if (tid < 64) sts_p(smem, tid + 512, pv2);
        }
        __syncthreads();                         // P visible
        if (do_s) om_gemm(sb, smem, wid, lane);
        __syncthreads();                         // om_s visible

        // ---- gap 1: gathers 0..287 interleaved with epilogue half0 ----
#pragma unroll
        for (int u = 0; u < 2; u++) {
            bool act = do_s && (u == 0 || tid < 32);
            int t = tid + u * 256;
            uint4 q[4]; float w4[5];
            if (act) gather_ldg(om_s, n2, spbn, t, q, w4);
            epi_part(acc, out, n, spbase, 0, u, wid, lane);
            if (act) gather_fin(bufn, t, q, w4);
        }

        // ======== MMA half 1 (ch wid*64 + 32..63) ========
#pragma unroll
        for (int i = 0; i < 2; i++)
#pragma unroll
            for (int nt = 0; nt < 8; nt++)
#pragma unroll
                for (int r = 0; r < 4; r++) acc[i][nt][r] = 0.f;
        mma_half(wa_base + (uint32_t)(32 * RSTRIDE), ba4, bat, acc);

        // ---- gap 2: gathers 288..575 interleaved with epilogue half1 ----
#pragma unroll
        for (int u = 0; u < 2; u++) {
            bool act = do_s && (u == 0 || tid < 32);
            int t = 288 + tid + u * 256;
            uint4 q[4]; float w4[5];
            if (act) gather_ldg(om_s, n2, spbn, t, q, w4);
            epi_part(acc, out, n, spbase, 1, u, wid, lane);
            if (act) gather_fin(bufn, t, q, w4);
        }

        __syncthreads();                         // A(t+1) ready, om_s/P free
        cur ^= 1;
    }
}

// ---------------- launch ----------------
extern "C" void kernel_launch(void* const* d_in, const int* in_sizes, int n_in,
                              void* d_out, int out_size) {
    const float* x  = (const float*)d_in[0];
    const float* w1 = (const float*)d_in[1];
    const float* b1 = (const float*)d_in[2];
    const float* ow = (const float*)d_in[3];
    const float* ob = (const float*)d_in[4];
    const float* dw = (const float*)d_in[5];
    float* out = (float*)d_out;

    k_conv1<<<(NB * HH * WW / 2 + 255) / 256, 256>>>(x, w1, b1);

    cudaFuncSetAttribute(k_dcn, cudaFuncAttributeMaxDynamicSharedMemorySize, SM_TOTAL);
    k_dcn<<<GRID, 256, SM_TOTAL>>>(dw, ow, ob, out);
}